// round 7
// baseline (speedup 1.0000x reference)
#include <cuda_runtime.h>
#include <math.h>

#define BATCH 16
#define NA 21824            // total anchors per image: 16384+4096+1024+256+64
#define NV4 5456            // NA/4
#define NSORT 2048          // top-K buffer actually sorted + NMS'd
#define FULLMASK 0xffffffffu

// ---------------- scratch (device globals; no allocation allowed) ----------
__device__ float  g_scores[BATCH * NA];
__device__ int    g_classes[BATCH * NA];
__device__ float4 g_boxes[BATCH * NA];
__device__ unsigned g_hist[2][BATCH][2048];

struct DecodeParams {
    const float* cls[5];
    const float* reg[5];
    const float* ctr[5];
    const float* pos[5];
};

// ---------------- K1: decode (64 anchors per 256-thread block) -------------
#define DEC_ANCHORS 64
#define DEC_T 256
#define SM_STRIDE 88        // floats per anchor row in smem (16B aligned, low conflicts)

__global__ void __launch_bounds__(DEC_T) decode_kernel(DecodeParams P) {
    __shared__ float sd[DEC_ANCHORS * SM_STRIDE];
    __shared__ float svmax[DEC_ANCHORS];
    __shared__ int   scls[DEC_ANCHORS];

    int img = blockIdx.y;
    int A0  = blockIdx.x * DEC_ANCHORS;
    int tid = threadIdx.x;

    // zero the histogram scratch for the later kernels (stream-ordered)
    if (blockIdx.y == 0 && blockIdx.x < 64) {
        unsigned* hp = &g_hist[0][0][0];
        #pragma unroll
        for (int i = 0; i < 4; i++)
            hp[blockIdx.x * 1024 + i * 256 + tid] = 0;
    }

    int lev, off, HW;
    if      (A0 < 16384) { lev = 0; off = 0;     HW = 16384; }
    else if (A0 < 20480) { lev = 1; off = 16384; HW = 4096; }
    else if (A0 < 21504) { lev = 2; off = 20480; HW = 1024; }
    else if (A0 < 21760) { lev = 3; off = 21504; HW = 256; }
    else                 { lev = 4; off = 21760; HW = 64; }

    long base = (long)img * HW + (A0 - off);

    // stage 64 anchors x 80 floats = 1280 float4s, coalesced
    const float4* cf4 = reinterpret_cast<const float4*>(P.cls[lev]) + base * 20;
    #pragma unroll
    for (int r = 0; r < 5; r++) {
        int g = tid + r * DEC_T;          // 0..1279
        float4 q = cf4[g];
        int a = g / 20;
        int m = g - a * 20;
        *reinterpret_cast<float4*>(&sd[a * SM_STRIDE + m * 4]) = q;
    }
    __syncthreads();

    // scan: 4 threads per anchor, 20 logits each
    {
        int a = tid >> 2, p = tid & 3;
        const float4* row = reinterpret_cast<const float4*>(&sd[a * SM_STRIDE + p * 20]);
        float v = -INFINITY; int ci = 0x7fffffff;
        #pragma unroll
        for (int u = 0; u < 5; u++) {
            float4 q = row[u];
            int c = p * 20 + u * 4;
            if (q.x > v) { v = q.x; ci = c; }
            if (q.y > v) { v = q.y; ci = c + 1; }
            if (q.z > v) { v = q.z; ci = c + 2; }
            if (q.w > v) { v = q.w; ci = c + 3; }
        }
        #pragma unroll
        for (int o = 1; o < 4; o <<= 1) {
            float ov = __shfl_xor_sync(FULLMASK, v, o);
            int   oi = __shfl_xor_sync(FULLMASK, ci, o);
            if (ov > v || (ov == v && oi < ci)) { v = ov; ci = oi; }
        }
        if (p == 0) { svmax[a] = v; scls[a] = ci; }
    }
    __syncthreads();

    // epilogue: one anchor per thread (threads 0..63), coalesced loads/stores
    if (tid < DEC_ANCHORS) {
        long bi = base + tid;
        float ct = P.ctr[lev][bi];
        float v  = svmax[tid];
        float sm  = 1.f / (1.f + expf(-v));
        float sct = 1.f / (1.f + expf(-ct));
        float s   = sqrtf(sm * sct);

        float4 rg = reinterpret_cast<const float4*>(P.reg[lev])[bi];
        float2 pp = reinterpret_cast<const float2*>(P.pos[lev])[bi];
        float e0 = expf(rg.x), e1 = expf(rg.y), e2 = expf(rg.z), e3 = expf(rg.w);
        int x1 = max((int)(pp.x - e0), 0);
        int y1 = max((int)(pp.y - e1), 0);
        int x2 = min((int)(pp.x + e2), 1023);
        int y2 = min((int)(pp.y + e3), 1023);

        int gi = img * NA + A0 + tid;
        g_scores[gi]  = s;
        g_classes[gi] = scls[tid];
        g_boxes[gi]   = make_float4((float)x1, (float)y1, (float)x2, (float)y2);
    }
}

// ---------------- histogram helpers ---------------------------------------
__device__ __forceinline__ void hadd(unsigned* hist, unsigned bin, unsigned act) {
    unsigned m = __match_any_sync(act, bin);
    int lane = threadIdx.x & 31;
    if (lane == __ffs(m) - 1) atomicAdd(&hist[bin], (unsigned)__popc(m));
}

// find highest bin where suffix count crosses `need`; writes *outB, *outAbove.
// callable with >=64 threads; chunkSum is shared scratch[64].
__device__ __forceinline__ void find_bin(const unsigned* hist, unsigned need,
                                         unsigned* chunkSum, unsigned* outB,
                                         unsigned* outAbove, int tid) {
    if (tid < 64) {
        unsigned s = 0;
        for (int b = 0; b < 32; b++) s += hist[tid * 32 + b];
        chunkSum[tid] = s;
    }
    __syncthreads();
    if (tid == 0) {
        unsigned run = 0;
        for (int c = 63; c >= 0; c--) { unsigned t = chunkSum[c]; chunkSum[c] = run; run += t; }
    }
    __syncthreads();
    if (tid < 64) {
        unsigned above = chunkSum[tid];
        for (int b = tid * 32 + 31; b >= tid * 32; b--) {
            unsigned h = hist[b];
            if (above < need && above + h >= need) { *outB = (unsigned)b; *outAbove = above; }
            above += h;
        }
    }
    __syncthreads();
}

// ---------------- K2a: pass-1 histogram (top 11 bits), 16x4 blocks ---------
#define HIST_T 256
#define HIST_SLICES 4

__global__ void __launch_bounds__(HIST_T) hist1_kernel() {
    __shared__ unsigned h[2048];
    int img = blockIdx.y, tid = threadIdx.x;
    for (int i = tid; i < 2048; i += HIST_T) h[i] = 0;
    __syncthreads();

    const float4* sc4 = reinterpret_cast<const float4*>(g_scores + img * NA);
    #pragma unroll
    for (int it = 0; it < 6; it++) {
        int j = blockIdx.x * HIST_T + tid + it * (HIST_T * HIST_SLICES);
        bool valid = j < NV4;
        unsigned act = __ballot_sync(FULLMASK, valid);
        if (valid) {
            float4 q = sc4[j];
            hadd(h, __float_as_uint(q.x) >> 21, act);
            hadd(h, __float_as_uint(q.y) >> 21, act);
            hadd(h, __float_as_uint(q.z) >> 21, act);
            hadd(h, __float_as_uint(q.w) >> 21, act);
        }
    }
    __syncthreads();
    for (int b = tid; b < 2048; b += HIST_T) {
        unsigned s = h[b];
        if (s) atomicAdd(&g_hist[0][img][b], s);
    }
}

// ---------------- K2b: pass-2 histogram (bits 21..10 within bin b1) --------
__global__ void __launch_bounds__(HIST_T) hist2_kernel() {
    __shared__ unsigned h[2048];
    __shared__ unsigned chunkSum[64];
    __shared__ unsigned sB1, sAb1;
    int img = blockIdx.y, tid = threadIdx.x;

    find_bin(g_hist[0][img], 1024u, chunkSum, &sB1, &sAb1, tid);
    for (int i = tid; i < 2048; i += HIST_T) h[i] = 0;
    __syncthreads();
    unsigned b1 = sB1;

    const float4* sc4 = reinterpret_cast<const float4*>(g_scores + img * NA);
    #pragma unroll
    for (int it = 0; it < 6; it++) {
        int j = blockIdx.x * HIST_T + tid + it * (HIST_T * HIST_SLICES);
        bool valid = j < NV4;
        float4 q = valid ? sc4[j] : make_float4(0.f, 0.f, 0.f, 0.f);
        unsigned u;
        bool p; unsigned act;
        u = __float_as_uint(q.x); p = valid && ((u >> 21) == b1);
        act = __ballot_sync(FULLMASK, p); if (p) hadd(h, (u >> 10) & 0x7FF, act);
        u = __float_as_uint(q.y); p = valid && ((u >> 21) == b1);
        act = __ballot_sync(FULLMASK, p); if (p) hadd(h, (u >> 10) & 0x7FF, act);
        u = __float_as_uint(q.z); p = valid && ((u >> 21) == b1);
        act = __ballot_sync(FULLMASK, p); if (p) hadd(h, (u >> 10) & 0x7FF, act);
        u = __float_as_uint(q.w); p = valid && ((u >> 21) == b1);
        act = __ballot_sync(FULLMASK, p); if (p) hadd(h, (u >> 10) & 0x7FF, act);
    }
    __syncthreads();
    for (int b = tid; b < 2048; b += HIST_T) {
        unsigned s = h[b];
        if (s) atomicAdd(&g_hist[1][img][b], s);
    }
}

// ---------------- K3 (final): threshold + collect + sort-2048 + NMS --------
__device__ __forceinline__ void ce(unsigned long long& x, unsigned long long& y, bool up) {
    if (up ? (x < y) : (x > y)) { unsigned long long t = x; x = y; y = t; }
}

__device__ __forceinline__ bool iou_gt(float kx1, float ky1, float kx2, float ky2, float ka,
                                       float x1, float y1, float x2, float y2, float ca) {
    float xx1 = fmaxf(kx1, x1), yy1 = fmaxf(ky1, y1);
    float xx2 = fminf(kx2, x2), yy2 = fminf(ky2, y2);
    float inter = fmaxf(xx2 - xx1, 0.f) * fmaxf(yy2 - yy1, 0.f);
    float iou = inter / (ka + ca - inter);          // 0/0 -> NaN -> not suppressed (matches JAX)
    return iou > 0.6f;
}

#define FUSE_T 512
#define CHUNK 64

__global__ void __launch_bounds__(FUSE_T) final_kernel(float* __restrict__ out) {
    __shared__ unsigned long long a[NSORT];
    __shared__ unsigned chunkSum[64];
    __shared__ unsigned sB1, sAb1, sB2, sAb2, sCnt;
    // NMS shared state
    __shared__ float kx1[100], ky1[100], kx2[100], ky2[100], ka[100];
    __shared__ float cx1[CHUNK], cy1[CHUNK], cx2[CHUNK], cy2[CHUNK], car[CHUNK], csc[CHUNK];
    __shared__ int   ccl[CHUNK];
    __shared__ int   supk[CHUNK];
    __shared__ unsigned long long mask[CHUNK];
    __shared__ int   kl[CHUNK];
    __shared__ int   sNew, sNK, sDone;

    int img = blockIdx.x;
    int tid = threadIdx.x;
    int lane = tid & 31;
    const float4* sc4 = reinterpret_cast<const float4*>(g_scores + img * NA);

    // prefill output rows with -1
    for (int k = tid; k < 100; k += FUSE_T) {
        out[img * 100 + k]        = -1.f;
        out[1600 + img * 100 + k] = -1.f;
    }
    for (int q = tid; q < 400; q += FUSE_T)
        out[3200 + img * 400 + q] = -1.f;
    if (tid == 0) sCnt = 0;

    // ---- thresholds from prebuilt histograms ----
    find_bin(g_hist[0][img], 1024u, chunkSum, &sB1, &sAb1, tid);
    unsigned need2 = 1024u - sAb1;
    find_bin(g_hist[1][img], need2, chunkSum, &sB2, &sAb2, tid);
    unsigned B = (sB1 << 11) | sB2;    // 22-bit threshold key

    // ---- init sort buffer, then collect (ballot-aggregated counter) ----
    // key = (score_bits << 32) | (0x7FFFFFFF - anchor): ties -> ascending anchor,
    // matching the reference's stable sort over the concatenated pool.
    for (int i = tid; i < NSORT; i += FUSE_T) a[i] = 0x7FFFFFFFULL;   // pad: score 0, anchor 0
    __syncthreads();

    #pragma unroll
    for (int it = 0; it < 11; it++) {
        int j = tid + it * FUSE_T;
        bool valid = j < NV4;
        float4 q = valid ? sc4[j] : make_float4(0.f, 0.f, 0.f, 0.f);
        float v[4] = {q.x, q.y, q.z, q.w};
        #pragma unroll
        for (int c = 0; c < 4; c++) {
            unsigned u = __float_as_uint(v[c]);
            unsigned k22 = u >> 10;
            bool pass = valid && (k22 >= B);
            unsigned bal = __ballot_sync(FULLMASK, pass);
            if (bal) {
                int leader = __ffs(bal) - 1;
                unsigned bs = 0;
                if (lane == leader) bs = atomicAdd(&sCnt, (unsigned)__popc(bal));
                bs = __shfl_sync(FULLMASK, bs, leader);
                if (pass) {
                    unsigned s = bs + __popc(bal & ((1u << lane) - 1u));
                    if (k22 > B || s < NSORT) {
                        unsigned sl = (s < NSORT) ? s : (NSORT - 1);   // >B count < 1024, never clipped
                        a[sl] = ((unsigned long long)u << 32) | (unsigned)(0x7FFFFFFF - (4 * j + c));
                    }
                }
            }
        }
    }
    __syncthreads();

    // ---- bitonic sort 2048 (descending), 256 threads x 8 elements ----
    if (tid < 256) {
        int b = tid * 8;
        ulonglong2* A2 = reinterpret_cast<ulonglong2*>(a);
        unsigned long long v[8];
        #pragma unroll
        for (int e = 0; e < 4; e++) { ulonglong2 t2 = A2[b / 2 + e]; v[2*e] = t2.x; v[2*e+1] = t2.y; }
        ce(v[0], v[1], true);  ce(v[2], v[3], false);
        ce(v[4], v[5], true);  ce(v[6], v[7], false);
        ce(v[0], v[2], true);  ce(v[1], v[3], true);
        ce(v[4], v[6], false); ce(v[5], v[7], false);
        ce(v[0], v[1], true);  ce(v[2], v[3], true);
        ce(v[4], v[5], false); ce(v[6], v[7], false);
        bool u8 = ((b & 8) == 0);
        ce(v[0], v[4], u8); ce(v[1], v[5], u8); ce(v[2], v[6], u8); ce(v[3], v[7], u8);
        ce(v[0], v[2], u8); ce(v[1], v[3], u8); ce(v[4], v[6], u8); ce(v[5], v[7], u8);
        ce(v[0], v[1], u8); ce(v[2], v[3], u8); ce(v[4], v[5], u8); ce(v[6], v[7], u8);
        #pragma unroll
        for (int e = 0; e < 4; e++) A2[b / 2 + e] = make_ulonglong2(v[2*e], v[2*e+1]);
    }
    __syncthreads();

    for (int k = 16; k <= NSORT; k <<= 1) {
        for (int j = k >> 1; j >= 8; j >>= 1) {
            if (tid < 256) {
                ulonglong2* A2 = reinterpret_cast<ulonglong2*>(a);
                int p0 = tid * 4;
                int i0 = ((p0 & ~(j - 1)) << 1) | (p0 & (j - 1));
                bool up = ((i0 & k) == 0);
                ulonglong2 x01 = A2[i0 / 2],       x23 = A2[i0 / 2 + 1];
                ulonglong2 y01 = A2[(i0 + j) / 2], y23 = A2[(i0 + j) / 2 + 1];
                ce(x01.x, y01.x, up); ce(x01.y, y01.y, up);
                ce(x23.x, y23.x, up); ce(x23.y, y23.y, up);
                A2[i0 / 2] = x01;       A2[i0 / 2 + 1] = x23;
                A2[(i0 + j) / 2] = y01; A2[(i0 + j) / 2 + 1] = y23;
            }
            __syncthreads();
        }
        if (tid < 256) {
            ulonglong2* A2 = reinterpret_cast<ulonglong2*>(a);
            int b = tid * 8;
            bool up = ((b & k) == 0);
            unsigned long long v[8];
            #pragma unroll
            for (int e = 0; e < 4; e++) { ulonglong2 t2 = A2[b / 2 + e]; v[2*e] = t2.x; v[2*e+1] = t2.y; }
            ce(v[0], v[4], up); ce(v[1], v[5], up); ce(v[2], v[6], up); ce(v[3], v[7], up);
            ce(v[0], v[2], up); ce(v[1], v[3], up); ce(v[4], v[6], up); ce(v[5], v[7], up);
            ce(v[0], v[1], up); ce(v[2], v[3], up); ce(v[4], v[5], up); ce(v[6], v[7], up);
            #pragma unroll
            for (int e = 0; e < 4; e++) A2[b / 2 + e] = make_ulonglong2(v[2*e], v[2*e+1]);
        }
        __syncthreads();
    }

    // ---- NMS over sorted candidates in shared ----
    if (tid == 0) { sNK = 0; sDone = 0; }
    __syncthreads();

    for (int base = 0; base < NSORT; base += CHUNK) {
        if (sDone) break;

        if (tid < CHUNK) {
            supk[tid] = 0;
            mask[tid] = 0ULL;
            unsigned long long it = a[base + tid];
            float s = __uint_as_float((unsigned)(it >> 32));
            int anc = 0x7FFFFFFF - (int)(unsigned)(it & 0xffffffffULL);
            float4 bx = g_boxes[img * NA + anc];
            cx1[tid] = bx.x; cy1[tid] = bx.y; cx2[tid] = bx.z; cy2[tid] = bx.w;
            car[tid] = (bx.z - bx.x) * (bx.w - bx.y);
            ccl[tid] = g_classes[img * NA + anc];
            csc[tid] = s;
        }
        __syncthreads();

        int nk = sNK;
        {
            int c = tid & (CHUNK - 1);
            int part = tid >> 6;            // 0..7
            float x1 = cx1[c], y1 = cy1[c], x2 = cx2[c], y2 = cy2[c], ar = car[c];
            bool any = false;
            for (int j = part; j < nk; j += 8)
                any |= iou_gt(kx1[j], ky1[j], kx2[j], ky2[j], ka[j], x1, y1, x2, y2, ar);
            if (any) supk[c] = 1;           // benign race: all writers store 1
        }

        for (int p = tid; p < CHUNK * CHUNK; p += FUSE_T) {
            int c = p >> 6, j = p & (CHUNK - 1);
            if (c < j) {
                if (iou_gt(cx1[c], cy1[c], cx2[c], cy2[c], car[c],
                           cx1[j], cy1[j], cx2[j], cy2[j], car[j]))
                    atomicOr(&mask[c], 1ULL << j);
            }
        }
        __syncthreads();

        if (tid == 0) {
            unsigned long long sup = 0;
            int nnew = 0;
            int done = 0;
            for (int c = 0; c < CHUNK; c++) {
                if (csc[c] <= 0.01f) { done = 1; break; }      // sorted -> rest invalid
                if (supk[c] || ((sup >> c) & 1ULL)) continue;
                kl[nnew++] = c;
                sup |= mask[c];
                if (sNK + nnew == 100) { done = 1; break; }
            }
            sNew = nnew;
            if (done) sDone = 1;
        }
        __syncthreads();

        if (tid < sNew) {
            int c = kl[tid];
            int pos = sNK + tid;
            kx1[pos] = cx1[c]; ky1[pos] = cy1[c];
            kx2[pos] = cx2[c]; ky2[pos] = cy2[c];
            ka[pos]  = car[c];
            out[img * 100 + pos]        = csc[c];
            out[1600 + img * 100 + pos] = (float)ccl[c];
            int ob = 3200 + img * 400 + pos * 4;
            out[ob]     = cx1[c];
            out[ob + 1] = cy1[c];
            out[ob + 2] = cx2[c];
            out[ob + 3] = cy2[c];
        }
        __syncthreads();
        if (tid == 0) sNK += sNew;
        __syncthreads();
    }
}

// ---------------- launch ---------------------------------------------------
extern "C" void kernel_launch(void* const* d_in, const int* in_sizes, int n_in,
                              void* d_out, int out_size) {
    DecodeParams P;
    for (int l = 0; l < 5; l++) {
        P.cls[l] = (const float*)d_in[4 * l + 0];
        P.reg[l] = (const float*)d_in[4 * l + 1];
        P.ctr[l] = (const float*)d_in[4 * l + 2];
        P.pos[l] = (const float*)d_in[4 * l + 3];
    }
    dim3 dgrid(341, BATCH);
    decode_kernel<<<dgrid, DEC_T>>>(P);
    dim3 hgrid(HIST_SLICES, BATCH);
    hist1_kernel<<<hgrid, HIST_T>>>();
    hist2_kernel<<<hgrid, HIST_T>>>();
    final_kernel<<<16, FUSE_T>>>((float*)d_out);
}

// round 8
// speedup vs baseline: 1.4705x; 1.4705x over previous
#include <cuda_runtime.h>
#include <math.h>

#define BATCH 16
#define NA 21824            // total anchors per image: 16384+4096+1024+256+64
#define NV4 5456            // NA/4
#define NCAP 512            // collected candidate capacity (top-256 + tie bucket)
#define FULLMASK 0xffffffffu
#define PADKEY 0x7FFFFFFFULL   // score bits 0, anchor field 0x7FFFFFFF -> anchor 0

// ---------------- scratch (device globals; no allocation allowed) ----------
__device__ float  g_scores[BATCH * NA];
__device__ int    g_classes[BATCH * NA];
__device__ float4 g_boxes[BATCH * NA];
__device__ unsigned g_hist[2][BATCH][2048];

struct DecodeParams {
    const float* cls[5];
    const float* reg[5];
    const float* ctr[5];
    const float* pos[5];
};

// ---------------- K1: decode (64 anchors per 256-thread block) -------------
#define DEC_ANCHORS 64
#define DEC_T 256
#define SM_STRIDE 88        // floats per anchor row in smem (16B aligned, low conflicts)

__global__ void __launch_bounds__(DEC_T) decode_kernel(DecodeParams P) {
    __shared__ float sd[DEC_ANCHORS * SM_STRIDE];
    __shared__ float svmax[DEC_ANCHORS];
    __shared__ int   scls[DEC_ANCHORS];

    int img = blockIdx.y;
    int A0  = blockIdx.x * DEC_ANCHORS;
    int tid = threadIdx.x;

    // zero the histogram scratch for the later kernels (stream-ordered)
    if (blockIdx.y == 0 && blockIdx.x < 64) {
        unsigned* hp = &g_hist[0][0][0];
        #pragma unroll
        for (int i = 0; i < 4; i++)
            hp[blockIdx.x * 1024 + i * 256 + tid] = 0;
    }

    int lev, off, HW;
    if      (A0 < 16384) { lev = 0; off = 0;     HW = 16384; }
    else if (A0 < 20480) { lev = 1; off = 16384; HW = 4096; }
    else if (A0 < 21504) { lev = 2; off = 20480; HW = 1024; }
    else if (A0 < 21760) { lev = 3; off = 21504; HW = 256; }
    else                 { lev = 4; off = 21760; HW = 64; }

    long base = (long)img * HW + (A0 - off);

    // stage 64 anchors x 80 floats = 1280 float4s, coalesced
    const float4* cf4 = reinterpret_cast<const float4*>(P.cls[lev]) + base * 20;
    #pragma unroll
    for (int r = 0; r < 5; r++) {
        int g = tid + r * DEC_T;          // 0..1279
        float4 q = cf4[g];
        int a = g / 20;
        int m = g - a * 20;
        *reinterpret_cast<float4*>(&sd[a * SM_STRIDE + m * 4]) = q;
    }
    __syncthreads();

    // scan: 4 threads per anchor, 20 logits each
    {
        int a = tid >> 2, p = tid & 3;
        const float4* row = reinterpret_cast<const float4*>(&sd[a * SM_STRIDE + p * 20]);
        float v = -INFINITY; int ci = 0x7fffffff;
        #pragma unroll
        for (int u = 0; u < 5; u++) {
            float4 q = row[u];
            int c = p * 20 + u * 4;
            if (q.x > v) { v = q.x; ci = c; }
            if (q.y > v) { v = q.y; ci = c + 1; }
            if (q.z > v) { v = q.z; ci = c + 2; }
            if (q.w > v) { v = q.w; ci = c + 3; }
        }
        #pragma unroll
        for (int o = 1; o < 4; o <<= 1) {
            float ov = __shfl_xor_sync(FULLMASK, v, o);
            int   oi = __shfl_xor_sync(FULLMASK, ci, o);
            if (ov > v || (ov == v && oi < ci)) { v = ov; ci = oi; }
        }
        if (p == 0) { svmax[a] = v; scls[a] = ci; }
    }
    __syncthreads();

    // epilogue: one anchor per thread (threads 0..63), coalesced loads/stores
    if (tid < DEC_ANCHORS) {
        long bi = base + tid;
        float ct = P.ctr[lev][bi];
        float v  = svmax[tid];
        float sm  = 1.f / (1.f + expf(-v));
        float sct = 1.f / (1.f + expf(-ct));
        float s   = sqrtf(sm * sct);

        float4 rg = reinterpret_cast<const float4*>(P.reg[lev])[bi];
        float2 pp = reinterpret_cast<const float2*>(P.pos[lev])[bi];
        float e0 = expf(rg.x), e1 = expf(rg.y), e2 = expf(rg.z), e3 = expf(rg.w);
        int x1 = max((int)(pp.x - e0), 0);
        int y1 = max((int)(pp.y - e1), 0);
        int x2 = min((int)(pp.x + e2), 1023);
        int y2 = min((int)(pp.y + e3), 1023);

        int gi = img * NA + A0 + tid;
        g_scores[gi]  = s;
        g_classes[gi] = scls[tid];
        g_boxes[gi]   = make_float4((float)x1, (float)y1, (float)x2, (float)y2);
    }
}

// ---------------- histogram helpers ---------------------------------------
__device__ __forceinline__ void hadd(unsigned* hist, unsigned bin, unsigned act) {
    unsigned m = __match_any_sync(act, bin);
    int lane = threadIdx.x & 31;
    if (lane == __ffs(m) - 1) atomicAdd(&hist[bin], (unsigned)__popc(m));
}

// find highest bin where suffix count crosses `need`; writes *outB, *outAbove.
__device__ __forceinline__ void find_bin(const unsigned* hist, unsigned need,
                                         unsigned* chunkSum, unsigned* outB,
                                         unsigned* outAbove, int tid) {
    if (tid < 64) {
        unsigned s = 0;
        for (int b = 0; b < 32; b++) s += hist[tid * 32 + b];
        chunkSum[tid] = s;
    }
    __syncthreads();
    if (tid == 0) {
        unsigned run = 0;
        for (int c = 63; c >= 0; c--) { unsigned t = chunkSum[c]; chunkSum[c] = run; run += t; }
    }
    __syncthreads();
    if (tid < 64) {
        unsigned above = chunkSum[tid];
        for (int b = tid * 32 + 31; b >= tid * 32; b--) {
            unsigned h = hist[b];
            if (above < need && above + h >= need) { *outB = (unsigned)b; *outAbove = above; }
            above += h;
        }
    }
    __syncthreads();
}

// ---------------- K2a: pass-1 histogram (top 11 bits), 16x4 blocks ---------
#define HIST_T 256
#define HIST_SLICES 4

__global__ void __launch_bounds__(HIST_T) hist1_kernel() {
    __shared__ unsigned h[2048];
    int img = blockIdx.y, tid = threadIdx.x;
    for (int i = tid; i < 2048; i += HIST_T) h[i] = 0;
    __syncthreads();

    const float4* sc4 = reinterpret_cast<const float4*>(g_scores + img * NA);
    #pragma unroll
    for (int it = 0; it < 6; it++) {
        int j = blockIdx.x * HIST_T + tid + it * (HIST_T * HIST_SLICES);
        bool valid = j < NV4;
        unsigned act = __ballot_sync(FULLMASK, valid);
        if (valid) {
            float4 q = sc4[j];
            hadd(h, __float_as_uint(q.x) >> 21, act);
            hadd(h, __float_as_uint(q.y) >> 21, act);
            hadd(h, __float_as_uint(q.z) >> 21, act);
            hadd(h, __float_as_uint(q.w) >> 21, act);
        }
    }
    __syncthreads();
    for (int b = tid; b < 2048; b += HIST_T) {
        unsigned s = h[b];
        if (s) atomicAdd(&g_hist[0][img][b], s);
    }
}

// ---------------- K2b: pass-2 histogram (bits 21..10 within bin b1) --------
__global__ void __launch_bounds__(HIST_T) hist2_kernel() {
    __shared__ unsigned h[2048];
    __shared__ unsigned chunkSum[64];
    __shared__ unsigned sB1, sAb1;
    int img = blockIdx.y, tid = threadIdx.x;

    find_bin(g_hist[0][img], 256u, chunkSum, &sB1, &sAb1, tid);
    for (int i = tid; i < 2048; i += HIST_T) h[i] = 0;
    __syncthreads();
    unsigned b1 = sB1;

    const float4* sc4 = reinterpret_cast<const float4*>(g_scores + img * NA);
    #pragma unroll
    for (int it = 0; it < 6; it++) {
        int j = blockIdx.x * HIST_T + tid + it * (HIST_T * HIST_SLICES);
        bool valid = j < NV4;
        float4 q = valid ? sc4[j] : make_float4(0.f, 0.f, 0.f, 0.f);
        unsigned u;
        bool p; unsigned act;
        u = __float_as_uint(q.x); p = valid && ((u >> 21) == b1);
        act = __ballot_sync(FULLMASK, p); if (p) hadd(h, (u >> 10) & 0x7FF, act);
        u = __float_as_uint(q.y); p = valid && ((u >> 21) == b1);
        act = __ballot_sync(FULLMASK, p); if (p) hadd(h, (u >> 10) & 0x7FF, act);
        u = __float_as_uint(q.z); p = valid && ((u >> 21) == b1);
        act = __ballot_sync(FULLMASK, p); if (p) hadd(h, (u >> 10) & 0x7FF, act);
        u = __float_as_uint(q.w); p = valid && ((u >> 21) == b1);
        act = __ballot_sync(FULLMASK, p); if (p) hadd(h, (u >> 10) & 0x7FF, act);
    }
    __syncthreads();
    for (int b = tid; b < 2048; b += HIST_T) {
        unsigned s = h[b];
        if (s) atomicAdd(&g_hist[1][img][b], s);
    }
}

// ---------------- K3 (final): collect top-256(+ties) + rank sort + NMS -----
__device__ __forceinline__ bool iou_gt(float kx1, float ky1, float kx2, float ky2, float ka,
                                       float x1, float y1, float x2, float y2, float ca) {
    float xx1 = fmaxf(kx1, x1), yy1 = fmaxf(ky1, y1);
    float xx2 = fminf(kx2, x2), yy2 = fminf(ky2, y2);
    float inter = fmaxf(xx2 - xx1, 0.f) * fmaxf(yy2 - yy1, 0.f);
    float iou = inter / (ka + ca - inter);          // 0/0 -> NaN -> not suppressed (matches JAX)
    return iou > 0.6f;
}

#define FUSE_T 512
#define CHUNK 64

__global__ void __launch_bounds__(FUSE_T) final_kernel(float* __restrict__ out) {
    __shared__ unsigned long long keys[NCAP];
    __shared__ unsigned long long sorted[NCAP];
    __shared__ unsigned chunkSum[64];
    __shared__ unsigned sB1, sAb1, sB2, sAb2, sGt, sEq;
    // NMS shared state
    __shared__ float kx1[100], ky1[100], kx2[100], ky2[100], ka[100];
    __shared__ float cx1[CHUNK], cy1[CHUNK], cx2[CHUNK], cy2[CHUNK], car[CHUNK], csc[CHUNK];
    __shared__ int   ccl[CHUNK];
    __shared__ int   supk[CHUNK];
    __shared__ unsigned long long mask[CHUNK];
    __shared__ int   kl[CHUNK];
    __shared__ int   sNew, sNK, sDone;

    int img = blockIdx.x;
    int tid = threadIdx.x;
    int lane = tid & 31;
    unsigned lmlt = (1u << lane) - 1u;
    const float4* sc4 = reinterpret_cast<const float4*>(g_scores + img * NA);

    // prefill output rows with -1
    for (int k = tid; k < 100; k += FUSE_T) {
        out[img * 100 + k]        = -1.f;
        out[1600 + img * 100 + k] = -1.f;
    }
    for (int q = tid; q < 400; q += FUSE_T)
        out[3200 + img * 400 + q] = -1.f;
    if (tid == 0) { sGt = 0; sEq = 0; }
    keys[tid]   = PADKEY;
    sorted[tid] = PADKEY;

    // ---- thresholds from prebuilt histograms (need = 256) ----
    find_bin(g_hist[0][img], 256u, chunkSum, &sB1, &sAb1, tid);
    unsigned need2 = 256u - sAb1;
    find_bin(g_hist[1][img], need2, chunkSum, &sB2, &sAb2, tid);
    unsigned B = (sB1 << 11) | sB2;    // 22-bit threshold key

    // ---- collect: >B keys -> slots [0,256) (exact, count<256),
    //               ==B-bucket keys -> slots [256,512) (first-arrival; bucket
    //               population realistically << 256, so top-256 is covered) ----
    // key = (score_bits << 32) | (0x7FFFFFFF - anchor): ties -> ascending anchor,
    // matching the reference's stable sort over the concatenated pool.
    #pragma unroll
    for (int it = 0; it < 11; it++) {
        int j = tid + it * FUSE_T;
        bool valid = j < NV4;
        float4 q = valid ? sc4[j] : make_float4(0.f, 0.f, 0.f, 0.f);
        float v[4] = {q.x, q.y, q.z, q.w};
        #pragma unroll
        for (int c = 0; c < 4; c++) {
            unsigned u = __float_as_uint(v[c]);
            unsigned k22 = u >> 10;
            bool gt = valid && (k22 > B);
            bool eq = valid && (k22 == B);
            unsigned bg = __ballot_sync(FULLMASK, gt);
            unsigned bs = 0;
            if (bg) {
                int ld = __ffs(bg) - 1;
                if (lane == ld) bs = atomicAdd(&sGt, (unsigned)__popc(bg));
                bs = __shfl_sync(FULLMASK, bs, ld);
            }
            unsigned be = __ballot_sync(FULLMASK, eq);
            unsigned es = 0;
            if (be) {
                int ld = __ffs(be) - 1;
                if (lane == ld) es = atomicAdd(&sEq, (unsigned)__popc(be));
                es = __shfl_sync(FULLMASK, es, ld);
            }
            unsigned long long key = ((unsigned long long)u << 32) |
                                     (unsigned)(0x7FFFFFFF - (4 * j + c));
            if (gt) {
                unsigned s = bs + __popc(bg & lmlt);        // s < 256 guaranteed
                keys[s] = key;
            } else if (eq) {
                unsigned s = 256u + es + __popc(be & lmlt);
                if (s < NCAP) keys[s] = key;
            }
        }
    }
    __syncthreads();

    // ---- rank sort: thread tid owns keys[tid]; rank = #(strictly greater) ----
    {
        unsigned long long my = keys[tid];
        const ulonglong2* K2 = reinterpret_cast<const ulonglong2*>(keys);
        int rank = 0;
        #pragma unroll 8
        for (int j2 = 0; j2 < NCAP / 2; j2++) {
            ulonglong2 p = K2[j2];
            rank += (p.x > my) + (p.y > my);
        }
        sorted[rank] = my;    // unique real keys -> dense exact ranks; pads collide benignly
    }
    __syncthreads();

    // ---- NMS over sorted candidates ----
    if (tid == 0) { sNK = 0; sDone = 0; }
    __syncthreads();

    for (int base = 0; base < NCAP; base += CHUNK) {
        if (sDone) break;

        if (tid < CHUNK) {
            supk[tid] = 0;
            mask[tid] = 0ULL;
            unsigned long long it = sorted[base + tid];
            float s = __uint_as_float((unsigned)(it >> 32));
            int anc = 0x7FFFFFFF - (int)(unsigned)(it & 0xffffffffULL);
            float4 bx = g_boxes[img * NA + anc];
            cx1[tid] = bx.x; cy1[tid] = bx.y; cx2[tid] = bx.z; cy2[tid] = bx.w;
            car[tid] = (bx.z - bx.x) * (bx.w - bx.y);
            ccl[tid] = g_classes[img * NA + anc];
            csc[tid] = s;
        }
        __syncthreads();

        int nk = sNK;
        {
            int c = tid & (CHUNK - 1);
            int part = tid >> 6;            // 0..7
            float x1 = cx1[c], y1 = cy1[c], x2 = cx2[c], y2 = cy2[c], ar = car[c];
            bool any = false;
            for (int j = part; j < nk; j += 8)
                any |= iou_gt(kx1[j], ky1[j], kx2[j], ky2[j], ka[j], x1, y1, x2, y2, ar);
            if (any) supk[c] = 1;           // benign race: all writers store 1
        }

        for (int p = tid; p < CHUNK * CHUNK; p += FUSE_T) {
            int c = p >> 6, j = p & (CHUNK - 1);
            if (c < j) {
                if (iou_gt(cx1[c], cy1[c], cx2[c], cy2[c], car[c],
                           cx1[j], cy1[j], cx2[j], cy2[j], car[j]))
                    atomicOr(&mask[c], 1ULL << j);
            }
        }
        __syncthreads();

        if (tid == 0) {
            unsigned long long sup = 0;
            int nnew = 0;
            int done = 0;
            for (int c = 0; c < CHUNK; c++) {
                if (csc[c] <= 0.01f) { done = 1; break; }      // sorted -> rest invalid
                if (supk[c] || ((sup >> c) & 1ULL)) continue;
                kl[nnew++] = c;
                sup |= mask[c];
                if (sNK + nnew == 100) { done = 1; break; }
            }
            sNew = nnew;
            if (done) sDone = 1;
        }
        __syncthreads();

        if (tid < sNew) {
            int c = kl[tid];
            int pos = sNK + tid;
            kx1[pos] = cx1[c]; ky1[pos] = cy1[c];
            kx2[pos] = cx2[c]; ky2[pos] = cy2[c];
            ka[pos]  = car[c];
            out[img * 100 + pos]        = csc[c];
            out[1600 + img * 100 + pos] = (float)ccl[c];
            int ob = 3200 + img * 400 + pos * 4;
            out[ob]     = cx1[c];
            out[ob + 1] = cy1[c];
            out[ob + 2] = cx2[c];
            out[ob + 3] = cy2[c];
        }
        __syncthreads();
        if (tid == 0) sNK += sNew;
        __syncthreads();
    }
}

// ---------------- launch ---------------------------------------------------
extern "C" void kernel_launch(void* const* d_in, const int* in_sizes, int n_in,
                              void* d_out, int out_size) {
    DecodeParams P;
    for (int l = 0; l < 5; l++) {
        P.cls[l] = (const float*)d_in[4 * l + 0];
        P.reg[l] = (const float*)d_in[4 * l + 1];
        P.ctr[l] = (const float*)d_in[4 * l + 2];
        P.pos[l] = (const float*)d_in[4 * l + 3];
    }
    dim3 dgrid(341, BATCH);
    decode_kernel<<<dgrid, DEC_T>>>(P);
    dim3 hgrid(HIST_SLICES, BATCH);
    hist1_kernel<<<hgrid, HIST_T>>>();
    hist2_kernel<<<hgrid, HIST_T>>>();
    final_kernel<<<16, FUSE_T>>>((float*)d_out);
}

// round 9
// speedup vs baseline: 1.5378x; 1.0458x over previous
#include <cuda_runtime.h>
#include <math.h>

#define BATCH 16
#define NA 21824            // total anchors per image: 16384+4096+1024+256+64
#define NV4 5456            // NA/4
#define NCAP 512            // collected candidate capacity (top-256 + tie bucket)
#define FULLMASK 0xffffffffu
#define PADKEY 0x7FFFFFFFULL   // score bits 0, anchor field 0x7FFFFFFF -> anchor 0

// ---------------- scratch (device globals; no allocation allowed) ----------
__device__ float  g_scores[BATCH * NA];
__device__ int    g_classes[BATCH * NA];
__device__ float4 g_boxes[BATCH * NA];
__device__ unsigned g_hist[2][BATCH][2048];
__device__ unsigned long long g_keys[BATCH][NCAP];
__device__ unsigned g_cnt[BATCH][2];       // [0]=count(>B), [1]=count(==B bucket)

struct DecodeParams {
    const float* cls[5];
    const float* reg[5];
    const float* ctr[5];
    const float* pos[5];
};

// ---------------- K1: decode (64 anchors per 256-thread block) -------------
#define DEC_ANCHORS 64
#define DEC_T 256
#define SM_STRIDE 88        // floats per anchor row in smem (16B aligned, low conflicts)

__global__ void __launch_bounds__(DEC_T) decode_kernel(DecodeParams P) {
    __shared__ float sd[DEC_ANCHORS * SM_STRIDE];
    __shared__ float svmax[DEC_ANCHORS];
    __shared__ int   scls[DEC_ANCHORS];

    int img = blockIdx.y;
    int A0  = blockIdx.x * DEC_ANCHORS;
    int tid = threadIdx.x;

    // zero scratch for the later kernels (stream-ordered)
    if (blockIdx.y == 0 && blockIdx.x < 64) {
        unsigned* hp = &g_hist[0][0][0];
        #pragma unroll
        for (int i = 0; i < 4; i++)
            hp[blockIdx.x * 1024 + i * 256 + tid] = 0;
    }
    if (blockIdx.y == 1 && blockIdx.x == 0 && tid < BATCH * 2)
        (&g_cnt[0][0])[tid] = 0;

    int lev, off, HW;
    if      (A0 < 16384) { lev = 0; off = 0;     HW = 16384; }
    else if (A0 < 20480) { lev = 1; off = 16384; HW = 4096; }
    else if (A0 < 21504) { lev = 2; off = 20480; HW = 1024; }
    else if (A0 < 21760) { lev = 3; off = 21504; HW = 256; }
    else                 { lev = 4; off = 21760; HW = 64; }

    long base = (long)img * HW + (A0 - off);

    // stage 64 anchors x 80 floats = 1280 float4s, coalesced
    const float4* cf4 = reinterpret_cast<const float4*>(P.cls[lev]) + base * 20;
    #pragma unroll
    for (int r = 0; r < 5; r++) {
        int g = tid + r * DEC_T;          // 0..1279
        float4 q = cf4[g];
        int a = g / 20;
        int m = g - a * 20;
        *reinterpret_cast<float4*>(&sd[a * SM_STRIDE + m * 4]) = q;
    }
    __syncthreads();

    // scan: 4 threads per anchor, 20 logits each
    {
        int a = tid >> 2, p = tid & 3;
        const float4* row = reinterpret_cast<const float4*>(&sd[a * SM_STRIDE + p * 20]);
        float v = -INFINITY; int ci = 0x7fffffff;
        #pragma unroll
        for (int u = 0; u < 5; u++) {
            float4 q = row[u];
            int c = p * 20 + u * 4;
            if (q.x > v) { v = q.x; ci = c; }
            if (q.y > v) { v = q.y; ci = c + 1; }
            if (q.z > v) { v = q.z; ci = c + 2; }
            if (q.w > v) { v = q.w; ci = c + 3; }
        }
        #pragma unroll
        for (int o = 1; o < 4; o <<= 1) {
            float ov = __shfl_xor_sync(FULLMASK, v, o);
            int   oi = __shfl_xor_sync(FULLMASK, ci, o);
            if (ov > v || (ov == v && oi < ci)) { v = ov; ci = oi; }
        }
        if (p == 0) { svmax[a] = v; scls[a] = ci; }
    }
    __syncthreads();

    // epilogue: one anchor per thread (threads 0..63), coalesced loads/stores
    if (tid < DEC_ANCHORS) {
        long bi = base + tid;
        float ct = P.ctr[lev][bi];
        float v  = svmax[tid];
        float sm  = 1.f / (1.f + expf(-v));
        float sct = 1.f / (1.f + expf(-ct));
        float s   = sqrtf(sm * sct);

        float4 rg = reinterpret_cast<const float4*>(P.reg[lev])[bi];
        float2 pp = reinterpret_cast<const float2*>(P.pos[lev])[bi];
        float e0 = expf(rg.x), e1 = expf(rg.y), e2 = expf(rg.z), e3 = expf(rg.w);
        int x1 = max((int)(pp.x - e0), 0);
        int y1 = max((int)(pp.y - e1), 0);
        int x2 = min((int)(pp.x + e2), 1023);
        int y2 = min((int)(pp.y + e3), 1023);

        int gi = img * NA + A0 + tid;
        g_scores[gi]  = s;
        g_classes[gi] = scls[tid];
        g_boxes[gi]   = make_float4((float)x1, (float)y1, (float)x2, (float)y2);
    }
}

// ---------------- histogram helpers ---------------------------------------
__device__ __forceinline__ void hadd(unsigned* hist, unsigned bin, unsigned act) {
    unsigned m = __match_any_sync(act, bin);
    int lane = threadIdx.x & 31;
    if (lane == __ffs(m) - 1) atomicAdd(&hist[bin], (unsigned)__popc(m));
}

// find highest bin where suffix count crosses `need`; writes *outB, *outAbove.
__device__ __forceinline__ void find_bin(const unsigned* hist, unsigned need,
                                         unsigned* chunkSum, unsigned* outB,
                                         unsigned* outAbove, int tid) {
    if (tid < 64) {
        unsigned s = 0;
        for (int b = 0; b < 32; b++) s += hist[tid * 32 + b];
        chunkSum[tid] = s;
    }
    __syncthreads();
    if (tid == 0) {
        unsigned run = 0;
        for (int c = 63; c >= 0; c--) { unsigned t = chunkSum[c]; chunkSum[c] = run; run += t; }
    }
    __syncthreads();
    if (tid < 64) {
        unsigned above = chunkSum[tid];
        for (int b = tid * 32 + 31; b >= tid * 32; b--) {
            unsigned h = hist[b];
            if (above < need && above + h >= need) { *outB = (unsigned)b; *outAbove = above; }
            above += h;
        }
    }
    __syncthreads();
}

#define HIST_T 256
#define HIST_SLICES 8
#define HIST_ROUNDS 3      // ceil(NV4 / (HIST_T*HIST_SLICES))

// ---------------- K2a: pass-1 histogram (top 11 bits) ----------------------
__global__ void __launch_bounds__(HIST_T) hist1_kernel() {
    __shared__ unsigned h[2048];
    int img = blockIdx.y, tid = threadIdx.x;
    for (int i = tid; i < 2048; i += HIST_T) h[i] = 0;
    __syncthreads();

    const float4* sc4 = reinterpret_cast<const float4*>(g_scores + img * NA);
    #pragma unroll
    for (int it = 0; it < HIST_ROUNDS; it++) {
        int j = blockIdx.x * HIST_T + tid + it * (HIST_T * HIST_SLICES);
        bool valid = j < NV4;
        unsigned act = __ballot_sync(FULLMASK, valid);
        if (valid) {
            float4 q = sc4[j];
            hadd(h, __float_as_uint(q.x) >> 21, act);
            hadd(h, __float_as_uint(q.y) >> 21, act);
            hadd(h, __float_as_uint(q.z) >> 21, act);
            hadd(h, __float_as_uint(q.w) >> 21, act);
        }
    }
    __syncthreads();
    for (int b = tid; b < 2048; b += HIST_T) {
        unsigned s = h[b];
        if (s) atomicAdd(&g_hist[0][img][b], s);
    }
}

// ---------------- K2b: pass-2 histogram (bits 21..10 within bin b1) --------
__global__ void __launch_bounds__(HIST_T) hist2_kernel() {
    __shared__ unsigned h[2048];
    __shared__ unsigned chunkSum[64];
    __shared__ unsigned sB1, sAb1;
    int img = blockIdx.y, tid = threadIdx.x;

    find_bin(g_hist[0][img], 256u, chunkSum, &sB1, &sAb1, tid);
    for (int i = tid; i < 2048; i += HIST_T) h[i] = 0;
    __syncthreads();
    unsigned b1 = sB1;

    const float4* sc4 = reinterpret_cast<const float4*>(g_scores + img * NA);
    #pragma unroll
    for (int it = 0; it < HIST_ROUNDS; it++) {
        int j = blockIdx.x * HIST_T + tid + it * (HIST_T * HIST_SLICES);
        bool valid = j < NV4;
        float4 q = valid ? sc4[j] : make_float4(0.f, 0.f, 0.f, 0.f);
        unsigned u;
        bool p; unsigned act;
        u = __float_as_uint(q.x); p = valid && ((u >> 21) == b1);
        act = __ballot_sync(FULLMASK, p); if (p) hadd(h, (u >> 10) & 0x7FF, act);
        u = __float_as_uint(q.y); p = valid && ((u >> 21) == b1);
        act = __ballot_sync(FULLMASK, p); if (p) hadd(h, (u >> 10) & 0x7FF, act);
        u = __float_as_uint(q.z); p = valid && ((u >> 21) == b1);
        act = __ballot_sync(FULLMASK, p); if (p) hadd(h, (u >> 10) & 0x7FF, act);
        u = __float_as_uint(q.w); p = valid && ((u >> 21) == b1);
        act = __ballot_sync(FULLMASK, p); if (p) hadd(h, (u >> 10) & 0x7FF, act);
    }
    __syncthreads();
    for (int b = tid; b < 2048; b += HIST_T) {
        unsigned s = h[b];
        if (s) atomicAdd(&g_hist[1][img][b], s);
    }
}

// ---------------- K2c: collect passing keys into global buffer -------------
__global__ void __launch_bounds__(HIST_T) collect_kernel() {
    __shared__ unsigned chunkSum[64];
    __shared__ unsigned sB1, sAb1, sB2, sAb2;
    int img = blockIdx.y, tid = threadIdx.x;
    int lane = tid & 31;
    unsigned lmlt = (1u << lane) - 1u;

    find_bin(g_hist[0][img], 256u, chunkSum, &sB1, &sAb1, tid);
    unsigned need2 = 256u - sAb1;
    find_bin(g_hist[1][img], need2, chunkSum, &sB2, &sAb2, tid);
    unsigned B = (sB1 << 11) | sB2;    // 22-bit threshold key

    const float4* sc4 = reinterpret_cast<const float4*>(g_scores + img * NA);
    #pragma unroll
    for (int it = 0; it < HIST_ROUNDS; it++) {
        int j = blockIdx.x * HIST_T + tid + it * (HIST_T * HIST_SLICES);
        bool valid = j < NV4;
        float4 q = valid ? sc4[j] : make_float4(0.f, 0.f, 0.f, 0.f);
        float v[4] = {q.x, q.y, q.z, q.w};
        #pragma unroll
        for (int c = 0; c < 4; c++) {
            unsigned u = __float_as_uint(v[c]);
            unsigned k22 = u >> 10;
            bool gt = valid && (k22 > B);
            bool eq = valid && (k22 == B);
            unsigned bg = __ballot_sync(FULLMASK, gt);
            unsigned bs = 0;
            if (bg) {
                int ld = __ffs(bg) - 1;
                if (lane == ld) bs = atomicAdd(&g_cnt[img][0], (unsigned)__popc(bg));
                bs = __shfl_sync(FULLMASK, bs, ld);
            }
            unsigned be = __ballot_sync(FULLMASK, eq);
            unsigned es = 0;
            if (be) {
                int ld = __ffs(be) - 1;
                if (lane == ld) es = atomicAdd(&g_cnt[img][1], (unsigned)__popc(be));
                es = __shfl_sync(FULLMASK, es, ld);
            }
            // key = (score_bits << 32) | (0x7FFFFFFF - anchor): ties -> ascending anchor,
            // matching the reference's stable sort over the concatenated pool.
            unsigned long long key = ((unsigned long long)u << 32) |
                                     (unsigned)(0x7FFFFFFF - (4 * j + c));
            if (gt) {
                unsigned s = bs + __popc(bg & lmlt);        // global >B count < 256 guaranteed
                g_keys[img][s] = key;
            } else if (eq) {
                unsigned s = 256u + es + __popc(be & lmlt); // tie bucket (first-arrival)
                if (s < NCAP) g_keys[img][s] = key;
            }
        }
    }
}

// ---------------- K3 (final): rank sort (<=512) + NMS ----------------------
__device__ __forceinline__ bool iou_gt(float kx1, float ky1, float kx2, float ky2, float ka,
                                       float x1, float y1, float x2, float y2, float ca) {
    float xx1 = fmaxf(kx1, x1), yy1 = fmaxf(ky1, y1);
    float xx2 = fminf(kx2, x2), yy2 = fminf(ky2, y2);
    float inter = fmaxf(xx2 - xx1, 0.f) * fmaxf(yy2 - yy1, 0.f);
    float iou = inter / (ka + ca - inter);          // 0/0 -> NaN -> not suppressed (matches JAX)
    return iou > 0.6f;
}

#define FUSE_T 512
#define CHUNK 64

__global__ void __launch_bounds__(FUSE_T) final_kernel(float* __restrict__ out) {
    __shared__ unsigned long long keys[NCAP];
    __shared__ unsigned long long sorted[NCAP];
    // NMS shared state
    __shared__ float kx1[100], ky1[100], kx2[100], ky2[100], ka[100];
    __shared__ float cx1[CHUNK], cy1[CHUNK], cx2[CHUNK], cy2[CHUNK], car[CHUNK], csc[CHUNK];
    __shared__ int   ccl[CHUNK];
    __shared__ int   supk[CHUNK];
    __shared__ unsigned long long mask[CHUNK];
    __shared__ int   kl[CHUNK];
    __shared__ int   sNew, sNK, sDone;

    int img = blockIdx.x;
    int tid = threadIdx.x;

    // prefill output rows with -1
    for (int k = tid; k < 100; k += FUSE_T) {
        out[img * 100 + k]        = -1.f;
        out[1600 + img * 100 + k] = -1.f;
    }
    for (int q = tid; q < 400; q += FUSE_T)
        out[3200 + img * 400 + q] = -1.f;

    // load keys (count-masked; stale/unwritten slots -> PADKEY)
    unsigned gt = g_cnt[img][0];
    unsigned eq = g_cnt[img][1];
    {
        bool real = (tid < 256) ? ((unsigned)tid < gt) : ((unsigned)(tid - 256) < eq);
        unsigned long long my = real ? g_keys[img][tid] : PADKEY;
        keys[tid]   = my;
        sorted[tid] = PADKEY;
    }
    __syncthreads();

    // rank sort: thread tid owns keys[tid]; rank = #(strictly greater)
    {
        unsigned long long my = keys[tid];
        const ulonglong2* K2 = reinterpret_cast<const ulonglong2*>(keys);
        int rank = 0;
        #pragma unroll 8
        for (int j2 = 0; j2 < NCAP / 2; j2++) {
            ulonglong2 p = K2[j2];
            rank += (p.x > my) + (p.y > my);
        }
        sorted[rank] = my;    // unique real keys -> dense exact ranks; pads collide benignly
    }
    __syncthreads();

    // NMS over sorted candidates
    if (tid == 0) { sNK = 0; sDone = 0; }
    __syncthreads();

    for (int base = 0; base < NCAP; base += CHUNK) {
        if (sDone) break;

        if (tid < CHUNK) {
            supk[tid] = 0;
            mask[tid] = 0ULL;
            unsigned long long it = sorted[base + tid];
            float s = __uint_as_float((unsigned)(it >> 32));
            int anc = 0x7FFFFFFF - (int)(unsigned)(it & 0xffffffffULL);
            float4 bx = g_boxes[img * NA + anc];
            cx1[tid] = bx.x; cy1[tid] = bx.y; cx2[tid] = bx.z; cy2[tid] = bx.w;
            car[tid] = (bx.z - bx.x) * (bx.w - bx.y);
            ccl[tid] = g_classes[img * NA + anc];
            csc[tid] = s;
        }
        __syncthreads();

        int nk = sNK;
        {
            int c = tid & (CHUNK - 1);
            int part = tid >> 6;            // 0..7
            float x1 = cx1[c], y1 = cy1[c], x2 = cx2[c], y2 = cy2[c], ar = car[c];
            bool any = false;
            for (int j = part; j < nk; j += 8)
                any |= iou_gt(kx1[j], ky1[j], kx2[j], ky2[j], ka[j], x1, y1, x2, y2, ar);
            if (any) supk[c] = 1;           // benign race: all writers store 1
        }

        for (int p = tid; p < CHUNK * CHUNK; p += FUSE_T) {
            int c = p >> 6, j = p & (CHUNK - 1);
            if (c < j) {
                if (iou_gt(cx1[c], cy1[c], cx2[c], cy2[c], car[c],
                           cx1[j], cy1[j], cx2[j], cy2[j], car[j]))
                    atomicOr(&mask[c], 1ULL << j);
            }
        }
        __syncthreads();

        if (tid == 0) {
            unsigned long long sup = 0;
            int nnew = 0;
            int done = 0;
            for (int c = 0; c < CHUNK; c++) {
                if (csc[c] <= 0.01f) { done = 1; break; }      // sorted -> rest invalid
                if (supk[c] || ((sup >> c) & 1ULL)) continue;
                kl[nnew++] = c;
                sup |= mask[c];
                if (sNK + nnew == 100) { done = 1; break; }
            }
            sNew = nnew;
            if (done) sDone = 1;
        }
        __syncthreads();

        if (tid < sNew) {
            int c = kl[tid];
            int pos = sNK + tid;
            kx1[pos] = cx1[c]; ky1[pos] = cy1[c];
            kx2[pos] = cx2[c]; ky2[pos] = cy2[c];
            ka[pos]  = car[c];
            out[img * 100 + pos]        = csc[c];
            out[1600 + img * 100 + pos] = (float)ccl[c];
            int ob = 3200 + img * 400 + pos * 4;
            out[ob]     = cx1[c];
            out[ob + 1] = cy1[c];
            out[ob + 2] = cx2[c];
            out[ob + 3] = cy2[c];
        }
        __syncthreads();
        if (tid == 0) sNK += sNew;
        __syncthreads();
    }
}

// ---------------- launch ---------------------------------------------------
extern "C" void kernel_launch(void* const* d_in, const int* in_sizes, int n_in,
                              void* d_out, int out_size) {
    DecodeParams P;
    for (int l = 0; l < 5; l++) {
        P.cls[l] = (const float*)d_in[4 * l + 0];
        P.reg[l] = (const float*)d_in[4 * l + 1];
        P.ctr[l] = (const float*)d_in[4 * l + 2];
        P.pos[l] = (const float*)d_in[4 * l + 3];
    }
    dim3 dgrid(341, BATCH);
    decode_kernel<<<dgrid, DEC_T>>>(P);
    dim3 hgrid(HIST_SLICES, BATCH);
    hist1_kernel<<<hgrid, HIST_T>>>();
    hist2_kernel<<<hgrid, HIST_T>>>();
    collect_kernel<<<hgrid, HIST_T>>>();
    final_kernel<<<16, FUSE_T>>>((float*)d_out);
}

// round 11
// speedup vs baseline: 1.7063x; 1.1095x over previous
#include <cuda_runtime.h>
#include <math.h>

#define BATCH 16
#define NA 21824            // total anchors per image: 16384+4096+1024+256+64
#define NV4 5456            // NA/4
#define NCAP 512            // collected candidate capacity (top-256 + tie bucket)
#define FULLMASK 0xffffffffu
#define PADKEY 0x7FFFFFFFULL   // score bits 0, anchor field 0x7FFFFFFF -> anchor 0

// ---------------- scratch (device globals; zero-initialized at load) -------
// Every launch leaves these zeroed again (final_kernel self-cleans), so the
// pipeline is deterministic across harness replays.
__device__ float  g_scores[BATCH * NA];
__device__ int    g_classes[BATCH * NA];
__device__ float4 g_boxes[BATCH * NA];
__device__ unsigned g_hist[2][BATCH][2048];
__device__ unsigned long long g_keys[BATCH][NCAP];
__device__ unsigned g_cnt[BATCH][2];       // [0]=count(>B), [1]=count(==B bucket)

struct DecodeParams {
    const float* cls[5];
    const float* reg[5];
    const float* ctr[5];
    const float* pos[5];
};

// warp-aggregated histogram add (all 32 lanes active)
__device__ __forceinline__ void hadd(unsigned* hist, unsigned bin) {
    unsigned m = __match_any_sync(FULLMASK, bin);
    int lane = threadIdx.x & 31;
    if (lane == __ffs(m) - 1) atomicAdd(&hist[bin], (unsigned)__popc(m));
}

// ---------------- K1: decode (64 anchors per 256-thread block) -------------
#define DEC_ANCHORS 64
#define DEC_T 256
#define SM_STRIDE 88        // floats per anchor row in smem (16B aligned, low conflicts)

__global__ void __launch_bounds__(DEC_T) decode_kernel(DecodeParams P) {
    __shared__ float sd[DEC_ANCHORS * SM_STRIDE];
    __shared__ float svmax[DEC_ANCHORS];
    __shared__ int   scls[DEC_ANCHORS];

    int img = blockIdx.y;
    int A0  = blockIdx.x * DEC_ANCHORS;
    int tid = threadIdx.x;

    int lev, off, HW;
    if      (A0 < 16384) { lev = 0; off = 0;     HW = 16384; }
    else if (A0 < 20480) { lev = 1; off = 16384; HW = 4096; }
    else if (A0 < 21504) { lev = 2; off = 20480; HW = 1024; }
    else if (A0 < 21760) { lev = 3; off = 21504; HW = 256; }
    else                 { lev = 4; off = 21760; HW = 64; }

    long base = (long)img * HW + (A0 - off);

    // stage 64 anchors x 80 floats = 1280 float4s, coalesced
    const float4* cf4 = reinterpret_cast<const float4*>(P.cls[lev]) + base * 20;
    #pragma unroll
    for (int r = 0; r < 5; r++) {
        int g = tid + r * DEC_T;          // 0..1279
        float4 q = cf4[g];
        int a = g / 20;
        int m = g - a * 20;
        *reinterpret_cast<float4*>(&sd[a * SM_STRIDE + m * 4]) = q;
    }
    __syncthreads();

    // scan: 4 threads per anchor, 20 logits each
    {
        int a = tid >> 2, p = tid & 3;
        const float4* row = reinterpret_cast<const float4*>(&sd[a * SM_STRIDE + p * 20]);
        float v = -INFINITY; int ci = 0x7fffffff;
        #pragma unroll
        for (int u = 0; u < 5; u++) {
            float4 q = row[u];
            int c = p * 20 + u * 4;
            if (q.x > v) { v = q.x; ci = c; }
            if (q.y > v) { v = q.y; ci = c + 1; }
            if (q.z > v) { v = q.z; ci = c + 2; }
            if (q.w > v) { v = q.w; ci = c + 3; }
        }
        #pragma unroll
        for (int o = 1; o < 4; o <<= 1) {
            float ov = __shfl_xor_sync(FULLMASK, v, o);
            int   oi = __shfl_xor_sync(FULLMASK, ci, o);
            if (ov > v || (ov == v && oi < ci)) { v = ov; ci = oi; }
        }
        if (p == 0) { svmax[a] = v; scls[a] = ci; }
    }
    __syncthreads();

    // epilogue: one anchor per thread (threads 0..63, two full warps)
    if (tid < DEC_ANCHORS) {
        long bi = base + tid;
        float ct = P.ctr[lev][bi];
        float v  = svmax[tid];
        float sm  = 1.f / (1.f + expf(-v));
        float sct = 1.f / (1.f + expf(-ct));
        float s   = sqrtf(sm * sct);

        float4 rg = reinterpret_cast<const float4*>(P.reg[lev])[bi];
        float2 pp = reinterpret_cast<const float2*>(P.pos[lev])[bi];
        float e0 = expf(rg.x), e1 = expf(rg.y), e2 = expf(rg.z), e3 = expf(rg.w);
        int x1 = max((int)(pp.x - e0), 0);
        int y1 = max((int)(pp.y - e1), 0);
        int x2 = min((int)(pp.x + e2), 1023);
        int y2 = min((int)(pp.y + e3), 1023);

        int gi = img * NA + A0 + tid;
        g_scores[gi]  = s;
        g_classes[gi] = scls[tid];
        g_boxes[gi]   = make_float4((float)x1, (float)y1, (float)x2, (float)y2);

        // inline pass-1 histogram (top 11 bits of score pattern), warp-aggregated
        hadd(&g_hist[0][img][0], __float_as_uint(s) >> 21);
    }
}

// find highest bin where suffix count crosses `need`; writes *outB, *outAbove.
__device__ __forceinline__ void find_bin(const unsigned* hist, unsigned need,
                                         unsigned* chunkSum, unsigned* outB,
                                         unsigned* outAbove, int tid) {
    if (tid < 64) {
        unsigned s = 0;
        for (int b = 0; b < 32; b++) s += hist[tid * 32 + b];
        chunkSum[tid] = s;
    }
    __syncthreads();
    if (tid == 0) {
        unsigned run = 0;
        for (int c = 63; c >= 0; c--) { unsigned t = chunkSum[c]; chunkSum[c] = run; run += t; }
    }
    __syncthreads();
    if (tid < 64) {
        unsigned above = chunkSum[tid];
        for (int b = tid * 32 + 31; b >= tid * 32; b--) {
            unsigned h = hist[b];
            if (above < need && above + h >= need) { *outB = (unsigned)b; *outAbove = above; }
            above += h;
        }
    }
    __syncthreads();
}

#define HIST_T 256
#define HIST_SLICES 8
#define HIST_ROUNDS 3      // ceil(NV4 / (HIST_T*HIST_SLICES))

// ---------------- K2: pass-2 histogram (bits 21..10 within bin b1) ---------
__global__ void __launch_bounds__(HIST_T) hist2_kernel() {
    __shared__ unsigned h[2048];
    __shared__ unsigned chunkSum[64];
    __shared__ unsigned sB1, sAb1;
    int img = blockIdx.y, tid = threadIdx.x;

    find_bin(g_hist[0][img], 256u, chunkSum, &sB1, &sAb1, tid);
    for (int i = tid; i < 2048; i += HIST_T) h[i] = 0;
    __syncthreads();
    unsigned b1 = sB1;

    const float4* sc4 = reinterpret_cast<const float4*>(g_scores + img * NA);
    #pragma unroll
    for (int it = 0; it < HIST_ROUNDS; it++) {
        int j = blockIdx.x * HIST_T + tid + it * (HIST_T * HIST_SLICES);
        bool valid = j < NV4;
        float4 q = valid ? sc4[j] : make_float4(0.f, 0.f, 0.f, 0.f);
        unsigned u;
        // rare predicate -> plain shared atomics (no warp sync chains)
        u = __float_as_uint(q.x); if (valid && (u >> 21) == b1) atomicAdd(&h[(u >> 10) & 0x7FF], 1u);
        u = __float_as_uint(q.y); if (valid && (u >> 21) == b1) atomicAdd(&h[(u >> 10) & 0x7FF], 1u);
        u = __float_as_uint(q.z); if (valid && (u >> 21) == b1) atomicAdd(&h[(u >> 10) & 0x7FF], 1u);
        u = __float_as_uint(q.w); if (valid && (u >> 21) == b1) atomicAdd(&h[(u >> 10) & 0x7FF], 1u);
    }
    __syncthreads();
    for (int b = tid; b < 2048; b += HIST_T) {
        unsigned s = h[b];
        if (s) atomicAdd(&g_hist[1][img][b], s);
    }
}

// ---------------- K3: collect passing keys into global buffer --------------
__global__ void __launch_bounds__(HIST_T) collect_kernel() {
    __shared__ unsigned chunkSum[64];
    __shared__ unsigned sB1, sAb1, sB2, sAb2;
    int img = blockIdx.y, tid = threadIdx.x;

    find_bin(g_hist[0][img], 256u, chunkSum, &sB1, &sAb1, tid);
    unsigned need2 = 256u - sAb1;
    find_bin(g_hist[1][img], need2, chunkSum, &sB2, &sAb2, tid);
    unsigned B = (sB1 << 11) | sB2;    // 22-bit threshold key

    const float4* sc4 = reinterpret_cast<const float4*>(g_scores + img * NA);
    #pragma unroll
    for (int it = 0; it < HIST_ROUNDS; it++) {
        int j = blockIdx.x * HIST_T + tid + it * (HIST_T * HIST_SLICES);
        bool valid = j < NV4;
        float4 q = valid ? sc4[j] : make_float4(0.f, 0.f, 0.f, 0.f);
        float v[4] = {q.x, q.y, q.z, q.w};
        #pragma unroll
        for (int c = 0; c < 4; c++) {
            unsigned u = __float_as_uint(v[c]);
            unsigned k22 = u >> 10;
            if (valid && k22 >= B) {
                // key = (score_bits << 32) | (0x7FFFFFFF - anchor): ties ->
                // ascending anchor, matching the reference's stable order.
                unsigned long long key = ((unsigned long long)u << 32) |
                                         (unsigned)(0x7FFFFFFF - (4 * j + c));
                if (k22 > B) {
                    unsigned s = atomicAdd(&g_cnt[img][0], 1u);   // global >B count < 256
                    g_keys[img][s] = key;
                } else {
                    unsigned s = atomicAdd(&g_cnt[img][1], 1u);   // tie bucket
                    if (256u + s < NCAP) g_keys[img][256u + s] = key;
                }
            }
        }
    }
}

// ---------------- K4 (final): rank sort (<=512) + NMS ----------------------
__device__ __forceinline__ bool iou_gt(float kx1, float ky1, float kx2, float ky2, float ka,
                                       float x1, float y1, float x2, float y2, float ca) {
    float xx1 = fmaxf(kx1, x1), yy1 = fmaxf(ky1, y1);
    float xx2 = fminf(kx2, x2), yy2 = fminf(ky2, y2);
    float inter = fmaxf(xx2 - xx1, 0.f) * fmaxf(yy2 - yy1, 0.f);
    float iou = inter / (ka + ca - inter);          // 0/0 -> NaN -> not suppressed (matches JAX)
    return iou > 0.6f;
}

#define FUSE_T 512
#define CHUNK 64

__global__ void __launch_bounds__(FUSE_T) final_kernel(float* __restrict__ out) {
    __shared__ unsigned long long keys[NCAP];
    __shared__ unsigned long long sorted[NCAP];
    // NMS shared state
    __shared__ float kx1[100], ky1[100], kx2[100], ky2[100], ka[100];
    __shared__ float cx1[CHUNK], cy1[CHUNK], cx2[CHUNK], cy2[CHUNK], car[CHUNK], csc[CHUNK];
    __shared__ int   ccl[CHUNK];
    __shared__ int   supk[CHUNK];
    __shared__ unsigned long long mask[CHUNK];
    __shared__ int   kl[CHUNK];
    __shared__ int   sNew, sNK, sDone;

    int img = blockIdx.x;
    int tid = threadIdx.x;

    // prefill output rows with -1
    for (int k = tid; k < 100; k += FUSE_T) {
        out[img * 100 + k]        = -1.f;
        out[1600 + img * 100 + k] = -1.f;
    }
    for (int q = tid; q < 400; q += FUSE_T)
        out[3200 + img * 400 + q] = -1.f;

    // load keys (count-masked; stale/unwritten slots -> PADKEY)
    unsigned gt = g_cnt[img][0];
    unsigned eq = g_cnt[img][1];
    {
        bool real = (tid < 256) ? ((unsigned)tid < gt) : ((unsigned)(tid - 256) < eq);
        unsigned long long my = real ? g_keys[img][tid] : PADKEY;
        keys[tid]   = my;
        sorted[tid] = PADKEY;
    }
    __syncthreads();

    // rank sort: thread tid owns keys[tid]; rank = #(strictly greater)
    {
        unsigned long long my = keys[tid];
        const ulonglong2* K2 = reinterpret_cast<const ulonglong2*>(keys);
        int rank = 0;
        #pragma unroll 8
        for (int j2 = 0; j2 < NCAP / 2; j2++) {
            ulonglong2 p = K2[j2];
            rank += (p.x > my) + (p.y > my);
        }
        sorted[rank] = my;    // unique real keys -> dense exact ranks; pads collide benignly
    }

    // self-clean scratch for the next launch (counts already consumed above;
    // every thread holds its key in registers, so g_keys can stay stale)
    for (int i = tid; i < 2048; i += FUSE_T) {
        g_hist[0][img][i] = 0;
        g_hist[1][img][i] = 0;
    }
    if (tid < 2) g_cnt[img][tid] = 0;
    __syncthreads();

    // NMS over sorted candidates
    if (tid == 0) { sNK = 0; sDone = 0; }
    __syncthreads();

    for (int base = 0; base < NCAP; base += CHUNK) {
        if (sDone) break;

        if (tid < CHUNK) {
            supk[tid] = 0;
            mask[tid] = 0ULL;
            unsigned long long it = sorted[base + tid];
            float s = __uint_as_float((unsigned)(it >> 32));
            int anc = 0x7FFFFFFF - (int)(unsigned)(it & 0xffffffffULL);
            float4 bx = g_boxes[img * NA + anc];
            cx1[tid] = bx.x; cy1[tid] = bx.y; cx2[tid] = bx.z; cy2[tid] = bx.w;
            car[tid] = (bx.z - bx.x) * (bx.w - bx.y);
            ccl[tid] = g_classes[img * NA + anc];
            csc[tid] = s;
        }
        __syncthreads();

        int nk = sNK;
        {
            int c = tid & (CHUNK - 1);
            int part = tid >> 6;            // 0..7
            float x1 = cx1[c], y1 = cy1[c], x2 = cx2[c], y2 = cy2[c], ar = car[c];
            bool any = false;
            for (int j = part; j < nk; j += 8)
                any |= iou_gt(kx1[j], ky1[j], kx2[j], ky2[j], ka[j], x1, y1, x2, y2, ar);
            if (any) supk[c] = 1;           // benign race: all writers store 1
        }

        for (int p = tid; p < CHUNK * CHUNK; p += FUSE_T) {
            int c = p >> 6, j = p & (CHUNK - 1);
            if (c < j) {
                if (iou_gt(cx1[c], cy1[c], cx2[c], cy2[c], car[c],
                           cx1[j], cy1[j], cx2[j], cy2[j], car[j]))
                    atomicOr(&mask[c], 1ULL << j);
            }
        }
        __syncthreads();

        if (tid == 0) {
            unsigned long long sup = 0;
            int nnew = 0;
            int done = 0;
            for (int c = 0; c < CHUNK; c++) {
                if (csc[c] <= 0.01f) { done = 1; break; }      // sorted -> rest invalid
                if (supk[c] || ((sup >> c) & 1ULL)) continue;
                kl[nnew++] = c;
                sup |= mask[c];
                if (sNK + nnew == 100) { done = 1; break; }
            }
            sNew = nnew;
            if (done) sDone = 1;
        }
        __syncthreads();

        if (tid < sNew) {
            int c = kl[tid];
            int pos = sNK + tid;
            kx1[pos] = cx1[c]; ky1[pos] = cy1[c];
            kx2[pos] = cx2[c]; ky2[pos] = cy2[c];
            ka[pos]  = car[c];
            out[img * 100 + pos]        = csc[c];
            out[1600 + img * 100 + pos] = (float)ccl[c];
            int ob = 3200 + img * 400 + pos * 4;
            out[ob]     = cx1[c];
            out[ob + 1] = cy1[c];
            out[ob + 2] = cx2[c];
            out[ob + 3] = cy2[c];
        }
        __syncthreads();
        if (tid == 0) sNK += sNew;
        __syncthreads();
    }
}

// ---------------- launch ---------------------------------------------------
extern "C" void kernel_launch(void* const* d_in, const int* in_sizes, int n_in,
                              void* d_out, int out_size) {
    DecodeParams P;
    for (int l = 0; l < 5; l++) {
        P.cls[l] = (const float*)d_in[4 * l + 0];
        P.reg[l] = (const float*)d_in[4 * l + 1];
        P.ctr[l] = (const float*)d_in[4 * l + 2];
        P.pos[l] = (const float*)d_in[4 * l + 3];
    }
    dim3 dgrid(341, BATCH);
    decode_kernel<<<dgrid, DEC_T>>>(P);
    dim3 hgrid(HIST_SLICES, BATCH);
    hist2_kernel<<<hgrid, HIST_T>>>();
    collect_kernel<<<hgrid, HIST_T>>>();
    final_kernel<<<16, FUSE_T>>>((float*)d_out);
}

// round 12
// speedup vs baseline: 1.8085x; 1.0599x over previous
#include <cuda_runtime.h>
#include <math.h>

#define BATCH 16
#define NA 21824            // total anchors per image: 16384+4096+1024+256+64
#define NV4 5456            // NA/4
#define NCAP 512            // collected candidate capacity (top-256 + tie bucket)
#define FULLMASK 0xffffffffu
#define PADKEY 0x7FFFFFFFULL   // score bits 0, anchor field 0x7FFFFFFF -> anchor 0

// ---------------- scratch (device globals; zero-initialized at load) -------
// Every launch leaves these zeroed again (final phase self-cleans), so the
// pipeline is deterministic across harness replays.
__device__ float  g_scores[BATCH * NA];
__device__ int    g_classes[BATCH * NA];
__device__ float4 g_boxes[BATCH * NA];
__device__ unsigned g_hist[2][BATCH][2048];
__device__ unsigned long long g_keys[BATCH][NCAP];
__device__ unsigned g_cnt[BATCH][2];       // [0]=count(>B), [1]=count(==B bucket)
__device__ unsigned g_bar1[BATCH];         // hist2-done arrivals (8 per image)
__device__ unsigned g_bar2[BATCH];         // collect-done arrivals (8 per image)

struct DecodeParams {
    const float* cls[5];
    const float* reg[5];
    const float* ctr[5];
    const float* pos[5];
};

// warp-aggregated histogram add (all 32 lanes active)
__device__ __forceinline__ void hadd(unsigned* hist, unsigned bin) {
    unsigned m = __match_any_sync(FULLMASK, bin);
    int lane = threadIdx.x & 31;
    if (lane == __ffs(m) - 1) atomicAdd(&hist[bin], (unsigned)__popc(m));
}

// ---------------- K1: decode (64 anchors per 256-thread block) -------------
#define DEC_ANCHORS 64
#define DEC_T 256
#define SM_STRIDE 88        // floats per anchor row in smem (16B aligned, low conflicts)

__global__ void __launch_bounds__(DEC_T) decode_kernel(DecodeParams P) {
    __shared__ float sd[DEC_ANCHORS * SM_STRIDE];
    __shared__ float svmax[DEC_ANCHORS];
    __shared__ int   scls[DEC_ANCHORS];

    int img = blockIdx.y;
    int A0  = blockIdx.x * DEC_ANCHORS;
    int tid = threadIdx.x;

    int lev, off, HW;
    if      (A0 < 16384) { lev = 0; off = 0;     HW = 16384; }
    else if (A0 < 20480) { lev = 1; off = 16384; HW = 4096; }
    else if (A0 < 21504) { lev = 2; off = 20480; HW = 1024; }
    else if (A0 < 21760) { lev = 3; off = 21504; HW = 256; }
    else                 { lev = 4; off = 21760; HW = 64; }

    long base = (long)img * HW + (A0 - off);

    // stage 64 anchors x 80 floats = 1280 float4s, coalesced
    const float4* cf4 = reinterpret_cast<const float4*>(P.cls[lev]) + base * 20;
    #pragma unroll
    for (int r = 0; r < 5; r++) {
        int g = tid + r * DEC_T;          // 0..1279
        float4 q = cf4[g];
        int a = g / 20;
        int m = g - a * 20;
        *reinterpret_cast<float4*>(&sd[a * SM_STRIDE + m * 4]) = q;
    }
    __syncthreads();

    // scan: 4 threads per anchor, 20 logits each
    {
        int a = tid >> 2, p = tid & 3;
        const float4* row = reinterpret_cast<const float4*>(&sd[a * SM_STRIDE + p * 20]);
        float v = -INFINITY; int ci = 0x7fffffff;
        #pragma unroll
        for (int u = 0; u < 5; u++) {
            float4 q = row[u];
            int c = p * 20 + u * 4;
            if (q.x > v) { v = q.x; ci = c; }
            if (q.y > v) { v = q.y; ci = c + 1; }
            if (q.z > v) { v = q.z; ci = c + 2; }
            if (q.w > v) { v = q.w; ci = c + 3; }
        }
        #pragma unroll
        for (int o = 1; o < 4; o <<= 1) {
            float ov = __shfl_xor_sync(FULLMASK, v, o);
            int   oi = __shfl_xor_sync(FULLMASK, ci, o);
            if (ov > v || (ov == v && oi < ci)) { v = ov; ci = oi; }
        }
        if (p == 0) { svmax[a] = v; scls[a] = ci; }
    }
    __syncthreads();

    // epilogue: one anchor per thread (threads 0..63, two full warps)
    if (tid < DEC_ANCHORS) {
        long bi = base + tid;
        float ct = P.ctr[lev][bi];
        float v  = svmax[tid];
        float sm  = 1.f / (1.f + expf(-v));
        float sct = 1.f / (1.f + expf(-ct));
        float s   = sqrtf(sm * sct);

        float4 rg = reinterpret_cast<const float4*>(P.reg[lev])[bi];
        float2 pp = reinterpret_cast<const float2*>(P.pos[lev])[bi];
        float e0 = expf(rg.x), e1 = expf(rg.y), e2 = expf(rg.z), e3 = expf(rg.w);
        int x1 = max((int)(pp.x - e0), 0);
        int y1 = max((int)(pp.y - e1), 0);
        int x2 = min((int)(pp.x + e2), 1023);
        int y2 = min((int)(pp.y + e3), 1023);

        int gi = img * NA + A0 + tid;
        g_scores[gi]  = s;
        g_classes[gi] = scls[tid];
        g_boxes[gi]   = make_float4((float)x1, (float)y1, (float)x2, (float)y2);

        // inline pass-1 histogram (top 11 bits of score pattern), warp-aggregated
        hadd(&g_hist[0][img][0], __float_as_uint(s) >> 21);
    }
}

// find highest bin where suffix count crosses `need`; writes *outB, *outAbove.
__device__ __forceinline__ void find_bin(const unsigned* hist, unsigned need,
                                         unsigned* chunkSum, unsigned* outB,
                                         unsigned* outAbove, int tid) {
    if (tid < 64) {
        unsigned s = 0;
        for (int b = 0; b < 32; b++) s += hist[tid * 32 + b];
        chunkSum[tid] = s;
    }
    __syncthreads();
    if (tid == 0) {
        unsigned run = 0;
        for (int c = 63; c >= 0; c--) { unsigned t = chunkSum[c]; chunkSum[c] = run; run += t; }
    }
    __syncthreads();
    if (tid < 64) {
        unsigned above = chunkSum[tid];
        for (int b = tid * 32 + 31; b >= tid * 32; b--) {
            unsigned h = hist[b];
            if (above < need && above + h >= need) { *outB = (unsigned)b; *outAbove = above; }
            above += h;
        }
    }
    __syncthreads();
}

__device__ __forceinline__ bool iou_gt(float kx1, float ky1, float kx2, float ky2, float ka,
                                       float x1, float y1, float x2, float y2, float ca) {
    float xx1 = fmaxf(kx1, x1), yy1 = fmaxf(ky1, y1);
    float xx2 = fminf(kx2, x2), yy2 = fminf(ky2, y2);
    float inter = fmaxf(xx2 - xx1, 0.f) * fmaxf(yy2 - yy1, 0.f);
    float iou = inter / (ka + ca - inter);          // 0/0 -> NaN -> not suppressed (matches JAX)
    return iou > 0.6f;
}

// ---------------- K2 (fused): hist2 + collect + rank sort + NMS ------------
#define FUSE_T 256
#define FUSE_SLICES 8
#define FUSE_ROUNDS 3      // ceil(NV4 / (FUSE_T*FUSE_SLICES))
#define CHUNK 64

__global__ void __launch_bounds__(FUSE_T) fused_kernel(float* __restrict__ out) {
    __shared__ unsigned h[2048];
    __shared__ unsigned chunkSum[64];
    __shared__ unsigned sB1, sAb1, sB2, sAb2;
    __shared__ int sLast;
    __shared__ unsigned long long keys[NCAP];
    __shared__ unsigned long long sorted[NCAP];
    // NMS shared state
    __shared__ float kx1[100], ky1[100], kx2[100], ky2[100], ka[100];
    __shared__ float cx1[CHUNK], cy1[CHUNK], cx2[CHUNK], cy2[CHUNK], car[CHUNK], csc[CHUNK];
    __shared__ int   ccl[CHUNK];
    __shared__ int   supk[CHUNK];
    __shared__ unsigned long long mask[CHUNK];
    __shared__ int   kl[CHUNK];
    __shared__ unsigned sFlag[2];
    __shared__ int   sNew, sNK, sDone, sFast;

    int img = blockIdx.y;
    int tid = threadIdx.x;

    // ---- phase A: find b1, build hist2 (keep scores in registers) ----
    find_bin(g_hist[0][img], 256u, chunkSum, &sB1, &sAb1, tid);
    for (int i = tid; i < 2048; i += FUSE_T) h[i] = 0;
    __syncthreads();
    unsigned b1 = sB1;

    const float4* sc4 = reinterpret_cast<const float4*>(g_scores + img * NA);
    float4 qreg[FUSE_ROUNDS];
    #pragma unroll
    for (int it = 0; it < FUSE_ROUNDS; it++) {
        int j = blockIdx.x * FUSE_T + tid + it * (FUSE_T * FUSE_SLICES);
        bool valid = j < NV4;
        float4 q = valid ? sc4[j] : make_float4(0.f, 0.f, 0.f, 0.f);
        qreg[it] = q;
        unsigned u;
        u = __float_as_uint(q.x); if (valid && (u >> 21) == b1) atomicAdd(&h[(u >> 10) & 0x7FF], 1u);
        u = __float_as_uint(q.y); if (valid && (u >> 21) == b1) atomicAdd(&h[(u >> 10) & 0x7FF], 1u);
        u = __float_as_uint(q.z); if (valid && (u >> 21) == b1) atomicAdd(&h[(u >> 10) & 0x7FF], 1u);
        u = __float_as_uint(q.w); if (valid && (u >> 21) == b1) atomicAdd(&h[(u >> 10) & 0x7FF], 1u);
    }
    __syncthreads();
    for (int b = tid; b < 2048; b += FUSE_T) {
        unsigned s = h[b];
        if (s) atomicAdd(&g_hist[1][img][b], s);
    }

    // ---- barrier 1: all 8 slice-blocks of this image merged hist2 ----
    __threadfence();
    __syncthreads();
    if (tid == 0) {
        atomicAdd(&g_bar1[img], 1u);
        while (atomicAdd(&g_bar1[img], 0u) < 8u) { }
    }
    __syncthreads();
    __threadfence();

    // ---- phase B: threshold + collect (from registers) ----
    find_bin(g_hist[1][img], 256u - sAb1, chunkSum, &sB2, &sAb2, tid);
    unsigned B = (b1 << 11) | sB2;     // 22-bit threshold key

    #pragma unroll
    for (int it = 0; it < FUSE_ROUNDS; it++) {
        int j = blockIdx.x * FUSE_T + tid + it * (FUSE_T * FUSE_SLICES);
        bool valid = j < NV4;
        float4 q = qreg[it];
        float v[4] = {q.x, q.y, q.z, q.w};
        #pragma unroll
        for (int c = 0; c < 4; c++) {
            unsigned u = __float_as_uint(v[c]);
            unsigned k22 = u >> 10;
            if (valid && k22 >= B) {
                // key = (score_bits << 32) | (0x7FFFFFFF - anchor): ties ->
                // ascending anchor, matching the reference's stable order.
                unsigned long long key = ((unsigned long long)u << 32) |
                                         (unsigned)(0x7FFFFFFF - (4 * j + c));
                if (k22 > B) {
                    unsigned s = atomicAdd(&g_cnt[img][0], 1u);   // global >B count < 256
                    g_keys[img][s] = key;
                } else {
                    unsigned s = atomicAdd(&g_cnt[img][1], 1u);   // tie bucket
                    if (256u + s < NCAP) g_keys[img][256u + s] = key;
                }
            }
        }
    }

    // ---- barrier 2: last-done block of this image proceeds to final ----
    __threadfence();
    __syncthreads();
    if (tid == 0) {
        unsigned old = atomicAdd(&g_bar2[img], 1u);
        sLast = (old == 7u);
    }
    __syncthreads();
    if (!sLast) return;
    __threadfence();

    // =================== FINAL PHASE (one block per image) ===================

    // prefill output rows with -1
    for (int k = tid; k < 100; k += FUSE_T) {
        out[img * 100 + k]        = -1.f;
        out[1600 + img * 100 + k] = -1.f;
    }
    for (int q = tid; q < 400; q += FUSE_T)
        out[3200 + img * 400 + q] = -1.f;

    // load keys (count-masked; stale/unwritten slots -> PADKEY)
    unsigned gt = g_cnt[img][0];
    unsigned eq = g_cnt[img][1];
    {
        bool r0 = (unsigned)tid < gt;
        bool r1 = (unsigned)tid < eq;
        keys[tid]         = r0 ? g_keys[img][tid] : PADKEY;
        keys[tid + 256]   = r1 ? g_keys[img][tid + 256] : PADKEY;
        sorted[tid]       = PADKEY;
        sorted[tid + 256] = PADKEY;
    }

    // self-clean scratch for the next launch
    for (int i = tid; i < 2048; i += FUSE_T) {
        g_hist[0][img][i] = 0;
        g_hist[1][img][i] = 0;
    }
    if (tid < 2) g_cnt[img][tid] = 0;
    if (tid == 2) g_bar1[img] = 0;
    if (tid == 3) g_bar2[img] = 0;
    __syncthreads();

    // rank sort: 2 keys per thread; rank = #(strictly greater)
    {
        unsigned long long my0 = keys[tid];
        unsigned long long my1 = keys[tid + 256];
        const ulonglong2* K2 = reinterpret_cast<const ulonglong2*>(keys);
        int r0 = 0, r1 = 0;
        #pragma unroll 8
        for (int j2 = 0; j2 < NCAP / 2; j2++) {
            ulonglong2 p = K2[j2];
            r0 += (p.x > my0) + (p.y > my0);
            r1 += (p.x > my1) + (p.y > my1);
        }
        sorted[r0] = my0;   // unique real keys -> dense exact ranks; pads collide benignly
        sorted[r1] = my1;
    }
    __syncthreads();

    // NMS over sorted candidates
    if (tid == 0) { sNK = 0; sDone = 0; }
    __syncthreads();

    for (int base = 0; base < NCAP; base += CHUNK) {
        if (sDone) break;

        if (tid < CHUNK) {
            supk[tid] = 0;
            mask[tid] = 0ULL;
            unsigned long long it = sorted[base + tid];
            float s = __uint_as_float((unsigned)(it >> 32));
            int anc = 0x7FFFFFFF - (int)(unsigned)(it & 0xffffffffULL);
            float4 bx = g_boxes[img * NA + anc];
            cx1[tid] = bx.x; cy1[tid] = bx.y; cx2[tid] = bx.z; cy2[tid] = bx.w;
            car[tid] = (bx.z - bx.x) * (bx.w - bx.y);
            ccl[tid] = g_classes[img * NA + anc];
            csc[tid] = s;
        }
        __syncthreads();

        int nk = sNK;
        {
            int c = tid & (CHUNK - 1);
            int part = tid >> 6;            // 0..3
            float x1 = cx1[c], y1 = cy1[c], x2 = cx2[c], y2 = cy2[c], ar = car[c];
            bool any = false;
            for (int j = part; j < nk; j += 4)
                any |= iou_gt(kx1[j], ky1[j], kx2[j], ky2[j], ka[j], x1, y1, x2, y2, ar);
            if (any) supk[c] = 1;           // benign race: all writers store 1
        }

        for (int p = tid; p < CHUNK * CHUNK; p += FUSE_T) {
            int c = p >> 6, j = p & (CHUNK - 1);
            if (c < j) {
                if (iou_gt(cx1[c], cy1[c], cx2[c], cy2[c], car[c],
                           cx1[j], cy1[j], cx2[j], cy2[j], car[j]))
                    atomicOr(&mask[c], 1ULL << j);
            }
        }
        __syncthreads();

        // fast path: no suppression anywhere in chunk and all scores valid
        if (tid < CHUNK) {
            bool bad = supk[tid] || (mask[tid] != 0ULL) || (csc[tid] <= 0.01f);
            unsigned bb = __ballot_sync(FULLMASK, bad);
            if ((tid & 31) == 0) sFlag[tid >> 5] = bb;
        }
        __syncthreads();

        if (tid == 0) {
            if ((sFlag[0] | sFlag[1]) == 0u) {
                int nnew = min(CHUNK, 100 - sNK);
                sNew = nnew; sFast = 1;
                if (sNK + nnew >= 100) sDone = 1;
            } else {
                sFast = 0;
                unsigned long long sup = 0;
                int nnew = 0;
                int done = 0;
                for (int c = 0; c < CHUNK; c++) {
                    if (csc[c] <= 0.01f) { done = 1; break; }  // sorted -> rest invalid
                    if (supk[c] || ((sup >> c) & 1ULL)) continue;
                    kl[nnew++] = c;
                    sup |= mask[c];
                    if (sNK + nnew == 100) { done = 1; break; }
                }
                sNew = nnew;
                if (done) sDone = 1;
            }
        }
        __syncthreads();

        if (tid < sNew) {
            int c = sFast ? tid : kl[tid];
            int pos = sNK + tid;
            kx1[pos] = cx1[c]; ky1[pos] = cy1[c];
            kx2[pos] = cx2[c]; ky2[pos] = cy2[c];
            ka[pos]  = car[c];
            out[img * 100 + pos]        = csc[c];
            out[1600 + img * 100 + pos] = (float)ccl[c];
            int ob = 3200 + img * 400 + pos * 4;
            out[ob]     = cx1[c];
            out[ob + 1] = cy1[c];
            out[ob + 2] = cx2[c];
            out[ob + 3] = cy2[c];
        }
        __syncthreads();
        if (tid == 0) sNK += sNew;
        __syncthreads();
    }
}

// ---------------- launch ---------------------------------------------------
extern "C" void kernel_launch(void* const* d_in, const int* in_sizes, int n_in,
                              void* d_out, int out_size) {
    DecodeParams P;
    for (int l = 0; l < 5; l++) {
        P.cls[l] = (const float*)d_in[4 * l + 0];
        P.reg[l] = (const float*)d_in[4 * l + 1];
        P.ctr[l] = (const float*)d_in[4 * l + 2];
        P.pos[l] = (const float*)d_in[4 * l + 3];
    }
    dim3 dgrid(341, BATCH);
    decode_kernel<<<dgrid, DEC_T>>>(P);
    dim3 fgrid(FUSE_SLICES, BATCH);
    fused_kernel<<<fgrid, FUSE_T>>>((float*)d_out);
}

// round 13
// speedup vs baseline: 1.9432x; 1.0744x over previous
#include <cuda_runtime.h>
#include <math.h>

#define BATCH 16
#define NA 21824            // total anchors per image: 16384+4096+1024+256+64
#define NV4 5456            // NA/4
#define NCAP 512            // collected candidate capacity (top-256 + tie bucket)
#define FULLMASK 0xffffffffu
#define PADKEY 0x7FFFFFFFULL   // score bits 0, anchor field 0x7FFFFFFF -> anchor 0

// ---------------- scratch (device globals; zero-initialized at load) -------
// Every launch leaves these zeroed again (final phase self-cleans), so the
// pipeline is deterministic across harness replays.
__device__ float  g_scores[BATCH * NA];
__device__ int    g_classes[BATCH * NA];
__device__ float4 g_boxes[BATCH * NA];
__device__ unsigned g_hist[2][BATCH][2048];
__device__ unsigned long long g_keys[BATCH][NCAP];
__device__ unsigned g_cnt[BATCH][2];       // [0]=count(>B), [1]=count(==B bucket)
__device__ unsigned g_bar1[BATCH];         // hist2-done arrivals
__device__ unsigned g_bar2[BATCH];         // collect-done arrivals

struct DecodeParams {
    const float* cls[5];
    const float* reg[5];
    const float* ctr[5];
    const float* pos[5];
};

// warp-aggregated histogram add (all 32 lanes active)
__device__ __forceinline__ void hadd(unsigned* hist, unsigned bin) {
    unsigned m = __match_any_sync(FULLMASK, bin);
    int lane = threadIdx.x & 31;
    if (lane == __ffs(m) - 1) atomicAdd(&hist[bin], (unsigned)__popc(m));
}

// ---------------- K1: decode (64 anchors per 256-thread block) -------------
#define DEC_ANCHORS 64
#define DEC_T 256
#define SM_STRIDE 88        // floats per anchor row in smem (16B aligned, low conflicts)

__global__ void __launch_bounds__(DEC_T) decode_kernel(DecodeParams P) {
    __shared__ float sd[DEC_ANCHORS * SM_STRIDE];
    __shared__ float svmax[DEC_ANCHORS];
    __shared__ int   scls[DEC_ANCHORS];

    int img = blockIdx.y;
    int A0  = blockIdx.x * DEC_ANCHORS;
    int tid = threadIdx.x;

    int lev, off, HW;
    if      (A0 < 16384) { lev = 0; off = 0;     HW = 16384; }
    else if (A0 < 20480) { lev = 1; off = 16384; HW = 4096; }
    else if (A0 < 21504) { lev = 2; off = 20480; HW = 1024; }
    else if (A0 < 21760) { lev = 3; off = 21504; HW = 256; }
    else                 { lev = 4; off = 21760; HW = 64; }

    long base = (long)img * HW + (A0 - off);

    // stage 64 anchors x 80 floats = 1280 float4s, coalesced
    const float4* cf4 = reinterpret_cast<const float4*>(P.cls[lev]) + base * 20;
    #pragma unroll
    for (int r = 0; r < 5; r++) {
        int g = tid + r * DEC_T;          // 0..1279
        float4 q = cf4[g];
        int a = g / 20;
        int m = g - a * 20;
        *reinterpret_cast<float4*>(&sd[a * SM_STRIDE + m * 4]) = q;
    }
    __syncthreads();

    // scan: 4 threads per anchor, 20 logits each
    {
        int a = tid >> 2, p = tid & 3;
        const float4* row = reinterpret_cast<const float4*>(&sd[a * SM_STRIDE + p * 20]);
        float v = -INFINITY; int ci = 0x7fffffff;
        #pragma unroll
        for (int u = 0; u < 5; u++) {
            float4 q = row[u];
            int c = p * 20 + u * 4;
            if (q.x > v) { v = q.x; ci = c; }
            if (q.y > v) { v = q.y; ci = c + 1; }
            if (q.z > v) { v = q.z; ci = c + 2; }
            if (q.w > v) { v = q.w; ci = c + 3; }
        }
        #pragma unroll
        for (int o = 1; o < 4; o <<= 1) {
            float ov = __shfl_xor_sync(FULLMASK, v, o);
            int   oi = __shfl_xor_sync(FULLMASK, ci, o);
            if (ov > v || (ov == v && oi < ci)) { v = ov; ci = oi; }
        }
        if (p == 0) { svmax[a] = v; scls[a] = ci; }
    }
    __syncthreads();

    // epilogue: one anchor per thread (threads 0..63, two full warps)
    if (tid < DEC_ANCHORS) {
        long bi = base + tid;
        float ct = P.ctr[lev][bi];
        float v  = svmax[tid];
        float sm  = 1.f / (1.f + expf(-v));
        float sct = 1.f / (1.f + expf(-ct));
        float s   = sqrtf(sm * sct);

        float4 rg = reinterpret_cast<const float4*>(P.reg[lev])[bi];
        float2 pp = reinterpret_cast<const float2*>(P.pos[lev])[bi];
        float e0 = expf(rg.x), e1 = expf(rg.y), e2 = expf(rg.z), e3 = expf(rg.w);
        int x1 = max((int)(pp.x - e0), 0);
        int y1 = max((int)(pp.y - e1), 0);
        int x2 = min((int)(pp.x + e2), 1023);
        int y2 = min((int)(pp.y + e3), 1023);

        int gi = img * NA + A0 + tid;
        g_scores[gi]  = s;
        g_classes[gi] = scls[tid];
        g_boxes[gi]   = make_float4((float)x1, (float)y1, (float)x2, (float)y2);

        // inline pass-1 histogram (top 11 bits of score pattern), warp-aggregated
        hadd(&g_hist[0][img][0], __float_as_uint(s) >> 21);
    }
}

// find highest bin where suffix count crosses `need` (hist in SHARED memory)
__device__ __forceinline__ void find_bin_sh(const unsigned* hist, unsigned need,
                                            unsigned* chunkSum, unsigned* outB,
                                            unsigned* outAbove, int tid) {
    if (tid < 64) {
        unsigned s = 0;
        #pragma unroll
        for (int b = 0; b < 32; b++) s += hist[tid * 32 + b];
        chunkSum[tid] = s;
    }
    __syncthreads();
    if (tid == 0) {
        unsigned run = 0;
        for (int c = 63; c >= 0; c--) { unsigned t = chunkSum[c]; chunkSum[c] = run; run += t; }
    }
    __syncthreads();
    if (tid < 64) {
        unsigned above = chunkSum[tid];
        #pragma unroll
        for (int b = 31; b >= 0; b--) {
            unsigned h = hist[tid * 32 + b];
            if (above < need && above + h >= need) { *outB = (unsigned)(tid * 32 + b); *outAbove = above; }
            above += h;
        }
    }
    __syncthreads();
}

__device__ __forceinline__ bool iou_gt(float kx1, float ky1, float kx2, float ky2, float ka,
                                       float x1, float y1, float x2, float y2, float ca) {
    float xx1 = fmaxf(kx1, x1), yy1 = fmaxf(ky1, y1);
    float xx2 = fminf(kx2, x2), yy2 = fminf(ky2, y2);
    float inter = fmaxf(xx2 - xx1, 0.f) * fmaxf(yy2 - yy1, 0.f);
    float iou = inter / (ka + ca - inter);          // 0/0 -> NaN -> not suppressed (matches JAX)
    return iou > 0.6f;
}

// ---------------- K2 (fused): hist2 + collect + rank sort + NMS ------------
#define FUSE_T 512
#define FUSE_SLICES 4
#define FUSE_ROUNDS 3      // ceil(NV4 / (FUSE_T*FUSE_SLICES))
#define CHUNK 64

__global__ void __launch_bounds__(FUSE_T) fused_kernel(float* __restrict__ out) {
    __shared__ unsigned h[2048];
    __shared__ unsigned chunkSum[64];
    __shared__ unsigned sB1, sAb1, sB2, sAb2;
    __shared__ int sLast;
    __shared__ unsigned long long keys[NCAP];
    __shared__ unsigned long long sorted[NCAP];
    // preloaded candidate state (final phase)
    __shared__ float Bx1[NCAP], By1[NCAP], Bx2[NCAP], By2[NCAP], Sar[NCAP], Ssc[NCAP];
    __shared__ int   Scl[NCAP];
    // NMS shared state
    __shared__ float kx1[100], ky1[100], kx2[100], ky2[100], ka[100];
    __shared__ int   supk[CHUNK];
    __shared__ unsigned long long mask[CHUNK];
    __shared__ int   kl[CHUNK];
    __shared__ unsigned sFlag[2];
    __shared__ int   sNew, sNK, sDone, sFast;

    int img = blockIdx.y;
    int tid = threadIdx.x;

    // slice-0 block prefills the output rows (off the final critical path;
    // ordered before final writes by barrier 2 + fences)
    if (blockIdx.x == 0) {
        if (tid < 100) {
            out[img * 100 + tid]        = -1.f;
            out[1600 + img * 100 + tid] = -1.f;
        }
        for (int q = tid; q < 400; q += FUSE_T)
            out[3200 + img * 400 + q] = -1.f;
    }

    // ---- phase A: stage hist0 -> shared, find b1, build hist2 -------------
    for (int i = tid; i < 2048; i += FUSE_T) h[i] = g_hist[0][img][i];
    __syncthreads();
    find_bin_sh(h, 256u, chunkSum, &sB1, &sAb1, tid);
    unsigned b1 = sB1;
    for (int i = tid; i < 2048; i += FUSE_T) h[i] = 0;    // reuse as hist2 accumulator
    __syncthreads();

    const float4* sc4 = reinterpret_cast<const float4*>(g_scores + img * NA);
    float4 qreg[FUSE_ROUNDS];
    #pragma unroll
    for (int it = 0; it < FUSE_ROUNDS; it++) {
        int j = blockIdx.x * FUSE_T + tid + it * (FUSE_T * FUSE_SLICES);
        bool valid = j < NV4;
        float4 q = valid ? sc4[j] : make_float4(0.f, 0.f, 0.f, 0.f);
        qreg[it] = q;
        unsigned u;
        u = __float_as_uint(q.x); if (valid && (u >> 21) == b1) atomicAdd(&h[(u >> 10) & 0x7FF], 1u);
        u = __float_as_uint(q.y); if (valid && (u >> 21) == b1) atomicAdd(&h[(u >> 10) & 0x7FF], 1u);
        u = __float_as_uint(q.z); if (valid && (u >> 21) == b1) atomicAdd(&h[(u >> 10) & 0x7FF], 1u);
        u = __float_as_uint(q.w); if (valid && (u >> 21) == b1) atomicAdd(&h[(u >> 10) & 0x7FF], 1u);
    }
    __syncthreads();
    for (int b = tid; b < 2048; b += FUSE_T) {
        unsigned s = h[b];
        if (s) atomicAdd(&g_hist[1][img][b], s);
    }

    // ---- barrier 1: all slice-blocks of this image merged hist2 ----
    __threadfence();
    __syncthreads();
    if (tid == 0) {
        atomicAdd(&g_bar1[img], 1u);
        while (atomicAdd(&g_bar1[img], 0u) < (unsigned)FUSE_SLICES) { }
    }
    __syncthreads();
    __threadfence();

    // ---- phase B: stage hist1 -> shared, threshold + collect --------------
    for (int i = tid; i < 2048; i += FUSE_T) h[i] = g_hist[1][img][i];
    __syncthreads();
    find_bin_sh(h, 256u - sAb1, chunkSum, &sB2, &sAb2, tid);
    unsigned B = (b1 << 11) | sB2;     // 22-bit threshold key

    #pragma unroll
    for (int it = 0; it < FUSE_ROUNDS; it++) {
        int j = blockIdx.x * FUSE_T + tid + it * (FUSE_T * FUSE_SLICES);
        bool valid = j < NV4;
        float4 q = qreg[it];
        float v[4] = {q.x, q.y, q.z, q.w};
        #pragma unroll
        for (int c = 0; c < 4; c++) {
            unsigned u = __float_as_uint(v[c]);
            unsigned k22 = u >> 10;
            if (valid && k22 >= B) {
                // key = (score_bits << 32) | (0x7FFFFFFF - anchor): ties ->
                // ascending anchor, matching the reference's stable order.
                unsigned long long key = ((unsigned long long)u << 32) |
                                         (unsigned)(0x7FFFFFFF - (4 * j + c));
                if (k22 > B) {
                    unsigned s = atomicAdd(&g_cnt[img][0], 1u);   // global >B count < 256
                    g_keys[img][s] = key;
                } else {
                    unsigned s = atomicAdd(&g_cnt[img][1], 1u);   // tie bucket
                    if (256u + s < NCAP) g_keys[img][256u + s] = key;
                }
            }
        }
    }

    // ---- barrier 2: last-done block of this image proceeds to final ----
    __threadfence();
    __syncthreads();
    if (tid == 0) {
        unsigned old = atomicAdd(&g_bar2[img], 1u);
        sLast = (old == (unsigned)(FUSE_SLICES - 1));
    }
    __syncthreads();
    if (!sLast) return;
    __threadfence();

    // =================== FINAL PHASE (one block per image) ===================

    // load keys (count-masked; stale/unwritten slots -> PADKEY)
    unsigned gt = g_cnt[img][0];
    unsigned eq = g_cnt[img][1];
    {
        bool real = (tid < 256) ? ((unsigned)tid < gt) : ((unsigned)(tid - 256) < eq);
        keys[tid]   = real ? g_keys[img][tid] : PADKEY;
        sorted[tid] = PADKEY;
    }

    // self-clean scratch for the next launch
    for (int i = tid; i < 2048; i += FUSE_T) {
        g_hist[0][img][i] = 0;
        g_hist[1][img][i] = 0;
    }
    if (tid < 2) g_cnt[img][tid] = 0;
    if (tid == 2) g_bar1[img] = 0;
    if (tid == 3) g_bar2[img] = 0;
    __syncthreads();

    // rank sort: 1 key per thread; rank = #(strictly greater); broadcast LDS
    {
        unsigned long long my = keys[tid];
        const ulonglong2* K2 = reinterpret_cast<const ulonglong2*>(keys);
        int rank = 0;
        #pragma unroll 8
        for (int j2 = 0; j2 < NCAP / 2; j2++) {
            ulonglong2 p = K2[j2];
            rank += (p.x > my) + (p.y > my);
        }
        sorted[rank] = my;    // unique real keys -> dense exact ranks; pads collide benignly
    }
    __syncthreads();

    // pre-gather ALL candidate boxes/classes in one full-MLP pass
    {
        unsigned long long it = sorted[tid];
        float s = __uint_as_float((unsigned)(it >> 32));
        int anc = 0x7FFFFFFF - (int)(unsigned)(it & 0xffffffffULL);
        float4 bx = g_boxes[img * NA + anc];
        Bx1[tid] = bx.x; By1[tid] = bx.y; Bx2[tid] = bx.z; By2[tid] = bx.w;
        Sar[tid] = (bx.z - bx.x) * (bx.w - bx.y);
        Scl[tid] = g_classes[img * NA + anc];
        Ssc[tid] = s;
    }
    __syncthreads();

    // NMS over sorted candidates (all state in shared)
    if (tid == 0) { sNK = 0; sDone = 0; }
    __syncthreads();

    for (int base = 0; base < NCAP; base += CHUNK) {
        if (sDone) break;

        if (tid < CHUNK) { supk[tid] = 0; mask[tid] = 0ULL; }
        __syncthreads();

        int nk = sNK;
        {
            int c = tid & (CHUNK - 1);
            int part = tid >> 6;            // 0..7
            float x1 = Bx1[base + c], y1 = By1[base + c];
            float x2 = Bx2[base + c], y2 = By2[base + c], ar = Sar[base + c];
            bool any = false;
            for (int j = part; j < nk; j += 8)
                any |= iou_gt(kx1[j], ky1[j], kx2[j], ky2[j], ka[j], x1, y1, x2, y2, ar);
            if (any) supk[c] = 1;           // benign race: all writers store 1
        }

        for (int p = tid; p < CHUNK * CHUNK; p += FUSE_T) {
            int c = p >> 6, j = p & (CHUNK - 1);
            if (c < j) {
                if (iou_gt(Bx1[base + c], By1[base + c], Bx2[base + c], By2[base + c], Sar[base + c],
                           Bx1[base + j], By1[base + j], Bx2[base + j], By2[base + j], Sar[base + j]))
                    atomicOr(&mask[c], 1ULL << j);
            }
        }
        __syncthreads();

        // fast path: no suppression anywhere in chunk and all scores valid
        if (tid < CHUNK) {
            bool bad = supk[tid] || (mask[tid] != 0ULL) || (Ssc[base + tid] <= 0.01f);
            unsigned bb = __ballot_sync(FULLMASK, bad);
            if ((tid & 31) == 0) sFlag[tid >> 5] = bb;
        }
        __syncthreads();

        if (tid == 0) {
            if ((sFlag[0] | sFlag[1]) == 0u) {
                int nnew = min(CHUNK, 100 - sNK);
                sNew = nnew; sFast = 1;
                if (sNK + nnew >= 100) sDone = 1;
            } else {
                sFast = 0;
                unsigned long long sup = 0;
                int nnew = 0;
                int done = 0;
                for (int c = 0; c < CHUNK; c++) {
                    if (Ssc[base + c] <= 0.01f) { done = 1; break; }  // sorted -> rest invalid
                    if (supk[c] || ((sup >> c) & 1ULL)) continue;
                    kl[nnew++] = c;
                    sup |= mask[c];
                    if (sNK + nnew == 100) { done = 1; break; }
                }
                sNew = nnew;
                if (done) sDone = 1;
            }
        }
        __syncthreads();

        if (tid < sNew) {
            int c = base + (sFast ? tid : kl[tid]);
            int pos = sNK + tid;
            kx1[pos] = Bx1[c]; ky1[pos] = By1[c];
            kx2[pos] = Bx2[c]; ky2[pos] = By2[c];
            ka[pos]  = Sar[c];
            out[img * 100 + pos]        = Ssc[c];
            out[1600 + img * 100 + pos] = (float)Scl[c];
            int ob = 3200 + img * 400 + pos * 4;
            out[ob]     = Bx1[c];
            out[ob + 1] = By1[c];
            out[ob + 2] = Bx2[c];
            out[ob + 3] = By2[c];
        }
        __syncthreads();
        if (tid == 0) sNK += sNew;
        __syncthreads();
    }
}

// ---------------- launch ---------------------------------------------------
extern "C" void kernel_launch(void* const* d_in, const int* in_sizes, int n_in,
                              void* d_out, int out_size) {
    DecodeParams P;
    for (int l = 0; l < 5; l++) {
        P.cls[l] = (const float*)d_in[4 * l + 0];
        P.reg[l] = (const float*)d_in[4 * l + 1];
        P.ctr[l] = (const float*)d_in[4 * l + 2];
        P.pos[l] = (const float*)d_in[4 * l + 3];
    }
    dim3 dgrid(341, BATCH);
    decode_kernel<<<dgrid, DEC_T>>>(P);
    dim3 fgrid(FUSE_SLICES, BATCH);
    fused_kernel<<<fgrid, FUSE_T>>>((float*)d_out);
}